// round 14
// baseline (speedup 1.0000x reference)
#include <cuda_runtime.h>
#include <cuda_bf16.h>
#include <math.h>
#include <stdint.h>

#define B   4
#define S   1024
#define HID 1024
#define NH  16
#define NKV 4
#define DH  64
#define NQKV (HID + 2 * NKV * DH)   // 1536

// ---------------------------------------------------------------------------
// Scratch (allocation-free rule: __device__ globals)
// ---------------------------------------------------------------------------
__device__ __nv_bfloat16 g_Xhi[B*S*HID], g_Xlo[B*S*HID];
__device__ __nv_bfloat16 g_Qh[B*S*NH*DH],  g_Ql[B*S*NH*DH];
__device__ __nv_bfloat16 g_Kh[B*S*NKV*DH], g_Kl[B*S*NKV*DH];
__device__ __nv_bfloat16 g_Vh[B*S*NKV*DH], g_Vl[B*S*NKV*DH];
__device__ __nv_bfloat16 g_VTh[B*NKV*DH*S], g_VTl[B*NKV*DH*S];   // [b][hkv][d][s]
__device__ __nv_bfloat16 g_Ah[B*S*HID], g_Al[B*S*HID];
__device__ __nv_bfloat16 g_WqkvThi[NQKV*HID], g_WqkvTlo[NQKV*HID];
__device__ __nv_bfloat16 g_WoThi[HID*HID],    g_WoTlo[HID*HID];
__device__ uint2 g_Mbits[B*S*(S/64)];

// ---------------------------------------------------------------------------
// helpers
// ---------------------------------------------------------------------------
__device__ __forceinline__ uint32_t smem_u32(const void* p) {
    uint32_t a;
    asm("{ .reg .u64 t; cvta.to.shared.u64 t, %1; cvt.u32.u64 %0, t; }" : "=r"(a) : "l"(p));
    return a;
}
__device__ __forceinline__ void ldmx4(uint32_t* r, uint32_t addr) {
    asm volatile("ldmatrix.sync.aligned.m8n8.x4.shared.b16 {%0,%1,%2,%3}, [%4];"
                 : "=r"(r[0]), "=r"(r[1]), "=r"(r[2]), "=r"(r[3]) : "r"(addr));
}
__device__ __forceinline__ void mma16816(float* d, const uint32_t* a, const uint32_t* b) {
    asm volatile("mma.sync.aligned.m16n8k16.row.col.f32.bf16.bf16.f32 "
                 "{%0,%1,%2,%3}, {%4,%5,%6,%7}, {%8,%9}, {%0,%1,%2,%3};"
                 : "+f"(d[0]), "+f"(d[1]), "+f"(d[2]), "+f"(d[3])
                 : "r"(a[0]), "r"(a[1]), "r"(a[2]), "r"(a[3]), "r"(b[0]), "r"(b[1]));
}
__device__ __forceinline__ uint32_t pack_bf(float a, float b) {
    uint32_t r;
    asm("cvt.rn.bf16x2.f32 %0, %1, %2;" : "=r"(r) : "f"(b), "f"(a));
    return r;
}
__device__ __forceinline__ uint32_t pack_hi(float a, float b, float& la, float& lb) {
    uint32_t h = pack_bf(a, b);
    la = a - __uint_as_float(h << 16);
    lb = b - __uint_as_float(h & 0xFFFF0000u);
    return h;
}
__device__ __forceinline__ float fast_exp(float x) {
    const float LOG2E = 1.4426950408889634f;
    x = fmaxf(x, -87.0f);
    float z  = fmaf(x, LOG2E, 12582912.0f);
    float nf = z - 12582912.0f;
    float f  = fmaf(x, LOG2E, -nf);
    float p  = 1.33978436e-3f;
    p = fmaf(p, f, 9.67795525e-3f);
    p = fmaf(p, f, 5.55072727e-2f);
    p = fmaf(p, f, 2.40226419e-1f);
    p = fmaf(p, f, 6.93147182e-1f);
    p = fmaf(p, f, 1.0f);
    uint32_t sc = (uint32_t)(__float_as_int(z) + (127 - 0x4B400000)) << 23;
    return __uint_as_float(sc) * p;
}
#define CPA16(dst, src) asm volatile("cp.async.cg.shared.global [%0], [%1], 16;" :: "r"(dst), "l"(src))
#define CP_COMMIT()     asm volatile("cp.async.commit_group;")
#define CP_WAIT(n)      asm volatile("cp.async.wait_group %0;" :: "n"(n))

// ---------------------------------------------------------------------------
// prep kernels
// ---------------------------------------------------------------------------
__global__ void split_kernel(const float* __restrict__ x,
                             __nv_bfloat16* __restrict__ hi,
                             __nv_bfloat16* __restrict__ lo, int n4)
{
    int i = blockIdx.x * 256 + threadIdx.x;
    if (i >= n4) return;
    float4 v = ((const float4*)x)[i];
    float l0, l1, l2, l3;
    uint32_t h01 = pack_hi(v.x, v.y, l0, l1);
    uint32_t h23 = pack_hi(v.z, v.w, l2, l3);
    ((uint32_t*)hi)[2*i]   = h01;
    ((uint32_t*)hi)[2*i+1] = h23;
    ((uint32_t*)lo)[2*i]   = pack_bf(l0, l1);
    ((uint32_t*)lo)[2*i+1] = pack_bf(l2, l3);
}

__global__ void maskpack(const int* __restrict__ mask)
{
    int row = blockIdx.x;
    int w = threadIdx.x >> 5, lane = threadIdx.x & 31;
    int2 m = *(const int2*)(mask + (size_t)row * S + w * 64 + lane * 2);
    uint32_t b0 = __ballot_sync(0xffffffffu, m.x != 0);
    uint32_t b1 = __ballot_sync(0xffffffffu, m.y != 0);
    if (lane == 0) g_Mbits[row * (S/64) + w] = make_uint2(b0, b1);
}

__global__ void transpose_qkv(const float* __restrict__ Wq,
                              const float* __restrict__ Wk,
                              const float* __restrict__ Wv)
{
    __shared__ float t[32][33];
    int n0 = blockIdx.x * 32, k0 = blockIdx.y * 32;
    int tx = threadIdx.x, ty = threadIdx.y;
    const float* W;
    int N, nc;
    if (n0 < HID)            { W = Wq; N = HID; nc = n0; }
    else if (n0 < HID + 256) { W = Wk; N = 256; nc = n0 - HID; }
    else                     { W = Wv; N = 256; nc = n0 - HID - 256; }
    #pragma unroll
    for (int i = 0; i < 32; i += 8)
        t[ty + i][tx] = W[(size_t)(k0 + ty + i) * N + nc + tx];
    __syncthreads();
    #pragma unroll
    for (int i = 0; i < 32; i += 8) {
        float v = t[tx][ty + i];
        __nv_bfloat16 h = __float2bfloat16(v);
        size_t o = (size_t)(n0 + ty + i) * HID + k0 + tx;
        g_WqkvThi[o] = h;
        g_WqkvTlo[o] = __float2bfloat16(v - __bfloat162float(h));
    }
}

__global__ void transpose_split(const float* __restrict__ W,
                                __nv_bfloat16* __restrict__ hiT,
                                __nv_bfloat16* __restrict__ loT, int K, int N)
{
    __shared__ float t[32][33];
    int n0 = blockIdx.x * 32, k0 = blockIdx.y * 32;
    int tx = threadIdx.x, ty = threadIdx.y;
    #pragma unroll
    for (int i = 0; i < 32; i += 8)
        t[ty + i][tx] = W[(size_t)(k0 + ty + i) * N + n0 + tx];
    __syncthreads();
    #pragma unroll
    for (int i = 0; i < 32; i += 8) {
        float v = t[tx][ty + i];
        __nv_bfloat16 h = __float2bfloat16(v);
        size_t o = (size_t)(n0 + ty + i) * K + k0 + tx;
        hiT[o] = h;
        loT[o] = __float2bfloat16(v - __bfloat162float(h));
    }
}

__global__ void vt_transpose(const __nv_bfloat16* __restrict__ Vh,
                             const __nv_bfloat16* __restrict__ Vl,
                             __nv_bfloat16* __restrict__ VTh,
                             __nv_bfloat16* __restrict__ VTl)
{
    __shared__ __nv_bfloat16 th[32][34], tl[32][34];
    int s0 = blockIdx.x * 32, d0 = blockIdx.y * 32, bh = blockIdx.z;
    int bb = bh >> 2, hkv = bh & 3;
    int tx = threadIdx.x, ty = threadIdx.y;
    #pragma unroll
    for (int i = 0; i < 32; i += 8) {
        size_t src = (size_t)(bb * S + s0 + ty + i) * (NKV * DH) + hkv * DH + d0 + tx;
        th[ty + i][tx] = Vh[src];
        tl[ty + i][tx] = Vl[src];
    }
    __syncthreads();
    #pragma unroll
    for (int i = 0; i < 32; i += 8) {
        size_t dst = (size_t)(bh * DH + d0 + ty + i) * S + s0 + tx;
        VTh[dst] = th[tx][ty + i];
        VTl[dst] = tl[tx][ty + i];
    }
}

// ---------------------------------------------------------------------------
// GEMM cores: CTA tile 128(M) x 64(N), 2-stage cp.async, split-bf16.
// Smaller N-tile doubles grid size -> 86% wave utilization (vs 65%).
// Warps: 4(m) x 2(n), warp tile 32x32.
// ---------------------------------------------------------------------------
#define KC    32
#define ASTR  40
#define GT_A  (128 * ASTR)
#define GT_B  (64 * ASTR)
#define STG_E (2 * GT_A + 2 * GT_B)
#define GEMM_SMEM (2 * STG_E * 2)

#define GEMM_LOAD_STAGE(stg, k0_, Kd)                                            \
    _Pragma("unroll")                                                            \
    for (int i = 0; i < 6; i++) {                                                \
        int ch = tid + i * 256;                                                  \
        const __nv_bfloat16* src; uint32_t doff; size_t g;                       \
        if (ch < 1024) {                                                         \
            int tile = ch >> 9, rr = (ch >> 2) & 127, cc = (ch & 3) * 8;         \
            src = srcs[tile];                                                    \
            doff = (uint32_t)((stg) * STG_E + tile * GT_A + rr * ASTR + cc);     \
            g = (size_t)(m0 + rr) * (Kd) + (k0_) + cc;                           \
        } else {                                                                 \
            int ch2 = ch - 1024;                                                 \
            int tile = ch2 >> 8, rr = (ch2 >> 2) & 63, cc = (ch2 & 3) * 8;       \
            src = srcs[2 + tile];                                                \
            doff = (uint32_t)((stg) * STG_E + 2 * GT_A + tile * GT_B + rr * ASTR + cc); \
            g = (size_t)(n0 + rr) * (Kd) + (k0_) + cc;                           \
        }                                                                        \
        CPA16(sbase + doff * 2, src + g);                                        \
    }

#define GEMM_MAINLOOP(Ahi_, Alo_, Bhi_, Blo_, Kdim)                              \
    const __nv_bfloat16* srcs[4] = { Ahi_, Alo_, Bhi_, Blo_ };                   \
    const int KI = (Kdim) / KC;                                                  \
    GEMM_LOAD_STAGE(0, 0, Kdim)                                                  \
    CP_COMMIT();                                                                 \
    for (int kt = 0; kt < KI; kt++) {                                            \
        const int cur = kt & 1;                                                  \
        if (kt + 1 < KI) {                                                       \
            const int nxt = (kt + 1) & 1;                                        \
            int k0 = (kt + 1) * KC;                                              \
            GEMM_LOAD_STAGE(nxt, k0, Kdim)                                       \
            CP_COMMIT();                                                         \
            CP_WAIT(1);                                                          \
        } else {                                                                 \
            CP_WAIT(0);                                                          \
        }                                                                        \
        __syncthreads();                                                         \
        const uint32_t sAh = sbase + (uint32_t)(cur * STG_E) * 2;                \
        const uint32_t sAl = sAh + (uint32_t)GT_A * 2;                           \
        const uint32_t sBh = sAl + (uint32_t)GT_A * 2;                           \
        const uint32_t sBl = sBh + (uint32_t)GT_B * 2;                           \
        _Pragma("unroll")                                                        \
        for (int kk = 0; kk < KC; kk += 16) {                                    \
            uint32_t ahi[2][4], alo[2][4], bhi[2][4], blo[2][4];                 \
            _Pragma("unroll")                                                    \
            for (int mi = 0; mi < 2; mi++) {                                     \
                uint32_t off = ((wm + mi * 16 + a_row) * ASTR + kk + a_col) * 2; \
                ldmx4(ahi[mi], sAh + off);                                       \
                ldmx4(alo[mi], sAl + off);                                       \
            }                                                                    \
            _Pragma("unroll")                                                    \
            for (int t = 0; t < 2; t++) {                                        \
                uint32_t off = ((wn + t * 16 + b_row) * ASTR + kk + b_col) * 2;  \
                ldmx4(bhi[t], sBh + off);                                        \
                ldmx4(blo[t], sBl + off);                                        \
            }                                                                    \
            _Pragma("unroll")                                                    \
            for (int nj = 0; nj < 4; nj++) {                                     \
                const uint32_t* bh = &bhi[nj >> 1][(nj & 1) * 2];                \
                const uint32_t* bl = &blo[nj >> 1][(nj & 1) * 2];                \
                _Pragma("unroll")                                                \
                for (int mi = 0; mi < 2; mi++) {                                 \
                    mma16816(acc[mi][nj], ahi[mi], bh);                          \
                    mma16816(acc[mi][nj], ahi[mi], bl);                          \
                    mma16816(acc[mi][nj], alo[mi], bh);                          \
                }                                                                \
            }                                                                    \
        }                                                                        \
        __syncthreads();                                                         \
    }

#define GEMM_PREAMBLE                                                  \
    extern __shared__ __nv_bfloat16 smg[];                             \
    const uint32_t sbase = smem_u32(smg);                              \
    const int tid = threadIdx.x, wid = tid >> 5, lane = tid & 31;      \
    const int wm = (wid & 3) * 32;                                     \
    const int wn = (wid >> 2) * 32;                                    \
    const int m0 = blockIdx.y * 128, n0 = blockIdx.x * 64;             \
    const int a_row = (lane & 15), a_col = (lane >> 4) * 8;            \
    const int b_row = (lane & 7) + ((lane >> 4) << 3), b_col = ((lane >> 3) & 1) * 8; \
    float acc[2][4][4] = {};

__global__ void __launch_bounds__(256, 2)
gemm_qkv()
{
    GEMM_PREAMBLE
    GEMM_MAINLOOP(g_Xhi, g_Xlo, g_WqkvThi, g_WqkvTlo, HID)

    __nv_bfloat16 *dh, *dl;
    int ldcn, coff;
    if (n0 < HID)            { dh = g_Qh; dl = g_Ql; ldcn = HID; coff = n0; }
    else if (n0 < HID + 256) { dh = g_Kh; dl = g_Kl; ldcn = 256; coff = n0 - HID; }
    else                     { dh = g_Vh; dl = g_Vl; ldcn = 256; coff = n0 - HID - 256; }

    #pragma unroll
    for (int mi = 0; mi < 2; mi++) {
        int row = m0 + wm + mi * 16 + (lane >> 2);
        #pragma unroll
        for (int nj = 0; nj < 4; nj++) {
            int col = coff + wn + nj * 8 + (lane & 3) * 2;
            float l0, l1, l2, l3;
            uint32_t h01 = pack_hi(acc[mi][nj][0], acc[mi][nj][1], l0, l1);
            uint32_t h23 = pack_hi(acc[mi][nj][2], acc[mi][nj][3], l2, l3);
            *(uint32_t*)&dh[(size_t)row * ldcn + col]       = h01;
            *(uint32_t*)&dl[(size_t)row * ldcn + col]       = pack_bf(l0, l1);
            *(uint32_t*)&dh[(size_t)(row + 8) * ldcn + col] = h23;
            *(uint32_t*)&dl[(size_t)(row + 8) * ldcn + col] = pack_bf(l2, l3);
        }
    }
}

__global__ void __launch_bounds__(256, 2)
gemm_out(float* __restrict__ C)
{
    GEMM_PREAMBLE
    GEMM_MAINLOOP(g_Ah, g_Al, g_WoThi, g_WoTlo, HID)

    #pragma unroll
    for (int mi = 0; mi < 2; mi++) {
        int row = m0 + wm + mi * 16 + (lane >> 2);
        #pragma unroll
        for (int nj = 0; nj < 4; nj++) {
            int col = n0 + wn + nj * 8 + (lane & 3) * 2;
            *(float2*)&C[(size_t)row * HID + col]       = make_float2(acc[mi][nj][0], acc[mi][nj][1]);
            *(float2*)&C[(size_t)(row + 8) * HID + col] = make_float2(acc[mi][nj][2], acc[mi][nj][3]);
        }
    }
}

// ---------------------------------------------------------------------------
// Flash attention (unchanged from round 13 — 2 CTAs/SM)
// ---------------------------------------------------------------------------
#define TSTR 72
#define QT_E (128 * TSTR)
#define KV_E (64 * TSTR)
#define ATTN_SMEM ((2 * QT_E + 2 * 4 * KV_E) * 2)

__global__ void __launch_bounds__(256, 2)
attn_mma(const float* __restrict__ bias,
         __nv_bfloat16* __restrict__ Ah, __nv_bfloat16* __restrict__ Al)
{
    extern __shared__ __nv_bfloat16 smb[];
    const uint32_t aQh = smem_u32(smb);
    const uint32_t aQl = aQh + QT_E * 2;
    const uint32_t kvbase = aQl + QT_E * 2;

    const int tid = threadIdx.x, wid = tid >> 5, lane = tid & 31;
    const int qt = blockIdx.x, h = blockIdx.y, bb = blockIdx.z;
    const int hkv = h >> 2;
    const int wm = wid * 16;

    const int a_row = (lane & 15), a_col = (lane >> 4) * 8;
    const int b_row = (lane & 7) + ((lane >> 4) << 3), b_col = ((lane >> 3) & 1) * 8;
    const int r = lane >> 2, qc = (lane & 3) * 2;

    #pragma unroll
    for (int i = 0; i < 4; i++) {
        int idx = tid + i * 256;
        int rr = idx >> 3, c = (idx & 7) * 8;
        size_t g = (size_t)(bb * S + qt * 128 + rr) * (NH * DH) + h * DH + c;
        *(uint4*)(smb + rr * TSTR + c)          = *(const uint4*)&g_Qh[g];
        *(uint4*)(smb + QT_E + rr * TSTR + c)   = *(const uint4*)&g_Ql[g];
    }

    const __nv_bfloat16* kvsrc[4];
    kvsrc[0] = g_Kh + (size_t)bb * S * (NKV * DH) + hkv * DH;
    kvsrc[1] = g_Kl + (size_t)bb * S * (NKV * DH) + hkv * DH;
    kvsrc[2] = g_VTh + (size_t)((bb * NKV + hkv) * DH) * S;
    kvsrc[3] = g_VTl + (size_t)((bb * NKV + hkv) * DH) * S;

    const int ltile = tid >> 6;
    const int lidx = tid & 63;

    #pragma unroll
    for (int j = 0; j < 8; j++) {
        int ch = lidx + j * 64;
        int rr = ch >> 3, c = (ch & 7) * 8;
        uint32_t d = kvbase + (uint32_t)(ltile * KV_E + rr * TSTR + c) * 2;
        size_t g = (ltile < 2) ? (size_t)rr * (NKV * DH) + c
                               : (size_t)rr * S + c;
        CPA16(d, kvsrc[ltile] + g);
    }
    CP_COMMIT();

    float oacc[8][4] = {};
    float m0 = -INFINITY, m1 = -INFINITY, l0 = 0.f, l1 = 0.f;
    const int row0 = qt * 128 + wm + r;
    const float* bprow = bias + ((size_t)(bb * NH + h) * S + row0) * S + qc;
    const uint2* mrow0 = g_Mbits + (size_t)(bb * S + row0) * (S/64);
    const uint2* mrow1 = mrow0 + 8 * (S/64);

    for (int kt = 0; kt < S / 64; kt++) {
        const int cur = kt & 1;
        if (kt + 1 < S / 64) {
            const int nxt = (kt + 1) & 1;
            int s0 = (kt + 1) * 64;
            #pragma unroll
            for (int j = 0; j < 8; j++) {
                int ch = lidx + j * 64;
                int rr = ch >> 3, c = (ch & 7) * 8;
                uint32_t d = kvbase + (uint32_t)((nxt * 4 + ltile) * KV_E + rr * TSTR + c) * 2;
                size_t g = (ltile < 2) ? (size_t)(s0 + rr) * (NKV * DH) + c
                                       : (size_t)rr * S + s0 + c;
                CPA16(d, kvsrc[ltile] + g);
            }
            CP_COMMIT();
        }

        float2 bvA[8], bvB[8];
        const float* bp = bprow + (size_t)kt * 64;
        #pragma unroll
        for (int nj = 0; nj < 8; nj++) {
            bvA[nj] = *(const float2*)(bp + nj * 8);
            bvB[nj] = *(const float2*)(bp + 8 * S + nj * 8);
        }
        uint2 mwA = mrow0[kt], mwB = mrow1[kt];

        if (kt + 1 < S / 64) CP_WAIT(1); else CP_WAIT(0);
        __syncthreads();

        const uint32_t aKh = kvbase + (uint32_t)((cur * 4 + 0) * KV_E) * 2;
        const uint32_t aKl = kvbase + (uint32_t)((cur * 4 + 1) * KV_E) * 2;
        const uint32_t aVh = kvbase + (uint32_t)((cur * 4 + 2) * KV_E) * 2;
        const uint32_t aVl = kvbase + (uint32_t)((cur * 4 + 3) * KV_E) * 2;

        float sacc[8][4] = {};
        #pragma unroll
        for (int kk = 0; kk < 64; kk += 16) {
            uint32_t qh[4], ql[4], kh[4][4], kl[4][4];
            uint32_t offA = ((wm + a_row) * TSTR + kk + a_col) * 2;
            ldmx4(qh, aQh + offA);
            ldmx4(ql, aQl + offA);
            #pragma unroll
            for (int t = 0; t < 4; t++) {
                uint32_t offB = ((t * 16 + b_row) * TSTR + kk + b_col) * 2;
                ldmx4(kh[t], aKh + offB);
                ldmx4(kl[t], aKl + offB);
            }
            #pragma unroll
            for (int nj = 0; nj < 8; nj++)
                mma16816(sacc[nj], qh, &kh[nj >> 1][(nj & 1) * 2]);
            #pragma unroll
            for (int nj = 0; nj < 8; nj++)
                mma16816(sacc[nj], qh, &kl[nj >> 1][(nj & 1) * 2]);
            #pragma unroll
            for (int nj = 0; nj < 8; nj++)
                mma16816(sacc[nj], ql, &kh[nj >> 1][(nj & 1) * 2]);
        }

        #pragma unroll
        for (int nj = 0; nj < 8; nj++) {
            int bi = (lane & 3) + nj * 4;
            sacc[nj][0] = ((mwA.x >> bi) & 1) ? fmaf(sacc[nj][0], 0.125f, bvA[nj].x) : -1e9f;
            sacc[nj][1] = ((mwA.y >> bi) & 1) ? fmaf(sacc[nj][1], 0.125f, bvA[nj].y) : -1e9f;
            sacc[nj][2] = ((mwB.x >> bi) & 1) ? fmaf(sacc[nj][2], 0.125f, bvB[nj].x) : -1e9f;
            sacc[nj][3] = ((mwB.y >> bi) & 1) ? fmaf(sacc[nj][3], 0.125f, bvB[nj].y) : -1e9f;
        }

        float mx0 = -INFINITY, mx1 = -INFINITY;
        #pragma unroll
        for (int nj = 0; nj < 8; nj++) {
            mx0 = fmaxf(mx0, fmaxf(sacc[nj][0], sacc[nj][1]));
            mx1 = fmaxf(mx1, fmaxf(sacc[nj][2], sacc[nj][3]));
        }
        mx0 = fmaxf(mx0, __shfl_xor_sync(0xffffffffu, mx0, 1));
        mx0 = fmaxf(mx0, __shfl_xor_sync(0xffffffffu, mx0, 2));
        mx1 = fmaxf(mx1, __shfl_xor_sync(0xffffffffu, mx1, 1));
        mx1 = fmaxf(mx1, __shfl_xor_sync(0xffffffffu, mx1, 2));
        float mn0 = fmaxf(m0, mx0), mn1 = fmaxf(m1, mx1);
        float alpha0 = fast_exp(m0 - mn0), alpha1 = fast_exp(m1 - mn1);
        m0 = mn0; m1 = mn1;

        float ts0 = 0.f, ts1 = 0.f;
        uint32_t ph[8][2], pl[8][2];
        #pragma unroll
        for (int nj = 0; nj < 8; nj++) {
            float p0 = fast_exp(sacc[nj][0] - mn0);
            float p1 = fast_exp(sacc[nj][1] - mn0);
            float p2 = fast_exp(sacc[nj][2] - mn1);
            float p3 = fast_exp(sacc[nj][3] - mn1);
            ts0 += p0 + p1;
            ts1 += p2 + p3;
            float q0, q1, q2, q3;
            ph[nj][0] = pack_hi(p0, p1, q0, q1);
            ph[nj][1] = pack_hi(p2, p3, q2, q3);
            pl[nj][0] = pack_bf(q0, q1);
            pl[nj][1] = pack_bf(q2, q3);
        }
        ts0 += __shfl_xor_sync(0xffffffffu, ts0, 1);
        ts0 += __shfl_xor_sync(0xffffffffu, ts0, 2);
        ts1 += __shfl_xor_sync(0xffffffffu, ts1, 1);
        ts1 += __shfl_xor_sync(0xffffffffu, ts1, 2);
        l0 = l0 * alpha0 + ts0;
        l1 = l1 * alpha1 + ts1;

        #pragma unroll
        for (int nj = 0; nj < 8; nj++) {
            oacc[nj][0] *= alpha0; oacc[nj][1] *= alpha0;
            oacc[nj][2] *= alpha1; oacc[nj][3] *= alpha1;
        }

        #pragma unroll
        for (int kk = 0; kk < 64; kk += 16) {
            int nt = kk >> 3;
            uint32_t aPh[4] = { ph[nt][0], ph[nt][1], ph[nt + 1][0], ph[nt + 1][1] };
            uint32_t aPl[4] = { pl[nt][0], pl[nt][1], pl[nt + 1][0], pl[nt + 1][1] };
            uint32_t vh[4][4], vl[4][4];
            #pragma unroll
            for (int t = 0; t < 4; t++) {
                uint32_t offV = ((t * 16 + b_row) * TSTR + kk + b_col) * 2;
                ldmx4(vh[t], aVh + offV);
                ldmx4(vl[t], aVl + offV);
            }
            #pragma unroll
            for (int nj = 0; nj < 8; nj++)
                mma16816(oacc[nj], aPh, &vh[nj >> 1][(nj & 1) * 2]);
            #pragma unroll
            for (int nj = 0; nj < 8; nj++)
                mma16816(oacc[nj], aPh, &vl[nj >> 1][(nj & 1) * 2]);
            #pragma unroll
            for (int nj = 0; nj < 8; nj++)
                mma16816(oacc[nj], aPl, &vh[nj >> 1][(nj & 1) * 2]);
        }
        __syncthreads();
    }

    float inv0 = 1.0f / l0, inv1 = 1.0f / l1;
    int rowA = bb * S + qt * 128 + wm + r;
    #pragma unroll
    for (int nj = 0; nj < 8; nj++) {
        int col = h * DH + nj * 8 + qc;
        float q0, q1, q2, q3;
        uint32_t h01 = pack_hi(oacc[nj][0] * inv0, oacc[nj][1] * inv0, q0, q1);
        uint32_t h23 = pack_hi(oacc[nj][2] * inv1, oacc[nj][3] * inv1, q2, q3);
        *(uint32_t*)&Ah[(size_t)rowA * HID + col]       = h01;
        *(uint32_t*)&Al[(size_t)rowA * HID + col]       = pack_bf(q0, q1);
        *(uint32_t*)&Ah[(size_t)(rowA + 8) * HID + col] = h23;
        *(uint32_t*)&Al[(size_t)(rowA + 8) * HID + col] = pack_bf(q2, q3);
    }
}

// ---------------------------------------------------------------------------
extern "C" void kernel_launch(void* const* d_in, const int* in_sizes, int n_in,
                              void* d_out, int out_size)
{
    const float* X    = (const float*)d_in[0];
    const float* bias = (const float*)d_in[1];
    const int*   mask = (const int*  )d_in[2];
    const float* Wq   = (const float*)d_in[3];
    const float* Wk   = (const float*)d_in[4];
    const float* Wv   = (const float*)d_in[5];
    const float* Wo   = (const float*)d_in[6];
    float* out = (float*)d_out;

    __nv_bfloat16 *pXh, *pXl, *pVh, *pVl, *pVTh, *pVTl, *pAh, *pAl, *pWo, *pWo2;
    cudaGetSymbolAddress((void**)&pXh, g_Xhi);   cudaGetSymbolAddress((void**)&pXl, g_Xlo);
    cudaGetSymbolAddress((void**)&pVh, g_Vh);    cudaGetSymbolAddress((void**)&pVl, g_Vl);
    cudaGetSymbolAddress((void**)&pVTh, g_VTh);  cudaGetSymbolAddress((void**)&pVTl, g_VTl);
    cudaGetSymbolAddress((void**)&pAh, g_Ah);    cudaGetSymbolAddress((void**)&pAl, g_Al);
    cudaGetSymbolAddress((void**)&pWo, g_WoThi); cudaGetSymbolAddress((void**)&pWo2, g_WoTlo);

    cudaFuncSetAttribute(gemm_qkv, cudaFuncAttributeMaxDynamicSharedMemorySize, GEMM_SMEM);
    cudaFuncSetAttribute(gemm_out, cudaFuncAttributeMaxDynamicSharedMemorySize, GEMM_SMEM);
    cudaFuncSetAttribute(attn_mma, cudaFuncAttributeMaxDynamicSharedMemorySize, ATTN_SMEM);

    split_kernel<<<(B*S*HID/4 + 255)/256, 256>>>(X, pXh, pXl, B*S*HID/4);      // 0
    maskpack<<<B*S, 512>>>(mask);                                               // 1
    transpose_qkv<<<dim3(NQKV/32, HID/32), dim3(32, 8)>>>(Wq, Wk, Wv);          // 2
    gemm_qkv<<<dim3(NQKV/64, (B*S)/128), 256, GEMM_SMEM>>>();                   // 3
    vt_transpose<<<dim3(S/32, DH/32, B*NKV), dim3(32, 8)>>>(pVh, pVl, pVTh, pVTl); // 4
    attn_mma<<<dim3(S/128, NH, B), 256, ATTN_SMEM>>>(bias, pAh, pAl);           // 5
    transpose_split<<<dim3(HID/32, HID/32), dim3(32, 8)>>>(Wo, pWo, pWo2, HID, HID); // 6
    gemm_out<<<dim3(HID/64, (B*S)/128), 256, GEMM_SMEM>>>(out);                 // 7
}

// round 15
// speedup vs baseline: 1.3667x; 1.3667x over previous
#include <cuda_runtime.h>
#include <cuda_bf16.h>
#include <cuda_fp16.h>
#include <math.h>
#include <stdint.h>

#define B   4
#define S   1024
#define HID 1024
#define NH  16
#define NKV 4
#define DH  64
#define NQKV (HID + 2 * NKV * DH)   // 1536

// ---------------------------------------------------------------------------
// Scratch (allocation-free rule: __device__ globals)
// ---------------------------------------------------------------------------
__device__ __half g_Xf[B*S*HID];                 // fp16 hidden states
__device__ __half g_WqkvTf[NQKV*HID];            // fp16 [Wq^T;Wk^T;Wv^T]
__device__ __half g_WoTf[HID*HID];               // fp16 Wo^T
__device__ __half g_Af[B*S*HID];                 // fp16 attention output
__device__ __nv_bfloat16 g_Qh[B*S*NH*DH],  g_Ql[B*S*NH*DH];
__device__ __nv_bfloat16 g_Kh[B*S*NKV*DH], g_Kl[B*S*NKV*DH];
__device__ __nv_bfloat16 g_Vh[B*S*NKV*DH], g_Vl[B*S*NKV*DH];
__device__ __nv_bfloat16 g_VTh[B*NKV*DH*S], g_VTl[B*NKV*DH*S];   // [b][hkv][d][s]
__device__ uint2 g_Mbits[B*S*(S/64)];

// ---------------------------------------------------------------------------
// helpers
// ---------------------------------------------------------------------------
__device__ __forceinline__ uint32_t smem_u32(const void* p) {
    uint32_t a;
    asm("{ .reg .u64 t; cvta.to.shared.u64 t, %1; cvt.u32.u64 %0, t; }" : "=r"(a) : "l"(p));
    return a;
}
__device__ __forceinline__ void ldmx4(uint32_t* r, uint32_t addr) {
    asm volatile("ldmatrix.sync.aligned.m8n8.x4.shared.b16 {%0,%1,%2,%3}, [%4];"
                 : "=r"(r[0]), "=r"(r[1]), "=r"(r[2]), "=r"(r[3]) : "r"(addr));
}
// bf16 mma (attention)
__device__ __forceinline__ void mma16816(float* d, const uint32_t* a, const uint32_t* b) {
    asm volatile("mma.sync.aligned.m16n8k16.row.col.f32.bf16.bf16.f32 "
                 "{%0,%1,%2,%3}, {%4,%5,%6,%7}, {%8,%9}, {%0,%1,%2,%3};"
                 : "+f"(d[0]), "+f"(d[1]), "+f"(d[2]), "+f"(d[3])
                 : "r"(a[0]), "r"(a[1]), "r"(a[2]), "r"(a[3]), "r"(b[0]), "r"(b[1]));
}
// fp16 mma (projections)
__device__ __forceinline__ void mma16816h(float* d, const uint32_t* a, const uint32_t* b) {
    asm volatile("mma.sync.aligned.m16n8k16.row.col.f32.f16.f16.f32 "
                 "{%0,%1,%2,%3}, {%4,%5,%6,%7}, {%8,%9}, {%0,%1,%2,%3};"
                 : "+f"(d[0]), "+f"(d[1]), "+f"(d[2]), "+f"(d[3])
                 : "r"(a[0]), "r"(a[1]), "r"(a[2]), "r"(a[3]), "r"(b[0]), "r"(b[1]));
}
__device__ __forceinline__ uint32_t pack_bf(float a, float b) {
    uint32_t r;
    asm("cvt.rn.bf16x2.f32 %0, %1, %2;" : "=r"(r) : "f"(b), "f"(a));
    return r;
}
__device__ __forceinline__ uint32_t pack_hi(float a, float b, float& la, float& lb) {
    uint32_t h = pack_bf(a, b);
    la = a - __uint_as_float(h << 16);
    lb = b - __uint_as_float(h & 0xFFFF0000u);
    return h;
}
__device__ __forceinline__ uint32_t pack_f16(float a, float b) {
    uint32_t r;
    asm("cvt.rn.f16x2.f32 %0, %1, %2;" : "=r"(r) : "f"(b), "f"(a));
    return r;
}
__device__ __forceinline__ float fast_exp(float x) {
    const float LOG2E = 1.4426950408889634f;
    x = fmaxf(x, -87.0f);
    float z  = fmaf(x, LOG2E, 12582912.0f);
    float nf = z - 12582912.0f;
    float f  = fmaf(x, LOG2E, -nf);
    float p  = 1.33978436e-3f;
    p = fmaf(p, f, 9.67795525e-3f);
    p = fmaf(p, f, 5.55072727e-2f);
    p = fmaf(p, f, 2.40226419e-1f);
    p = fmaf(p, f, 6.93147182e-1f);
    p = fmaf(p, f, 1.0f);
    uint32_t sc = (uint32_t)(__float_as_int(z) + (127 - 0x4B400000)) << 23;
    return __uint_as_float(sc) * p;
}
#define CPA16(dst, src) asm volatile("cp.async.cg.shared.global [%0], [%1], 16;" :: "r"(dst), "l"(src))
#define CP_COMMIT()     asm volatile("cp.async.commit_group;")
#define CP_WAIT(n)      asm volatile("cp.async.wait_group %0;" :: "n"(n))

// ---------------------------------------------------------------------------
// prep kernels
// ---------------------------------------------------------------------------
__global__ void split_kernel(const float* __restrict__ x,
                             __half* __restrict__ hf, int n4)
{
    int i = blockIdx.x * 256 + threadIdx.x;
    if (i >= n4) return;
    float4 v = ((const float4*)x)[i];
    ((uint32_t*)hf)[2*i]   = pack_f16(v.x, v.y);
    ((uint32_t*)hf)[2*i+1] = pack_f16(v.z, v.w);
}

__global__ void maskpack(const int* __restrict__ mask)
{
    int row = blockIdx.x;
    int w = threadIdx.x >> 5, lane = threadIdx.x & 31;
    int2 m = *(const int2*)(mask + (size_t)row * S + w * 64 + lane * 2);
    uint32_t b0 = __ballot_sync(0xffffffffu, m.x != 0);
    uint32_t b1 = __ballot_sync(0xffffffffu, m.y != 0);
    if (lane == 0) g_Mbits[row * (S/64) + w] = make_uint2(b0, b1);
}

__global__ void transpose_qkv(const float* __restrict__ Wq,
                              const float* __restrict__ Wk,
                              const float* __restrict__ Wv)
{
    __shared__ float t[32][33];
    int n0 = blockIdx.x * 32, k0 = blockIdx.y * 32;
    int tx = threadIdx.x, ty = threadIdx.y;
    const float* W;
    int N, nc;
    if (n0 < HID)            { W = Wq; N = HID; nc = n0; }
    else if (n0 < HID + 256) { W = Wk; N = 256; nc = n0 - HID; }
    else                     { W = Wv; N = 256; nc = n0 - HID - 256; }
    #pragma unroll
    for (int i = 0; i < 32; i += 8)
        t[ty + i][tx] = W[(size_t)(k0 + ty + i) * N + nc + tx];
    __syncthreads();
    #pragma unroll
    for (int i = 0; i < 32; i += 8)
        g_WqkvTf[(size_t)(n0 + ty + i) * HID + k0 + tx] = __float2half(t[tx][ty + i]);
}

__global__ void transpose_wo(const float* __restrict__ W)
{
    __shared__ float t[32][33];
    int n0 = blockIdx.x * 32, k0 = blockIdx.y * 32;
    int tx = threadIdx.x, ty = threadIdx.y;
    #pragma unroll
    for (int i = 0; i < 32; i += 8)
        t[ty + i][tx] = W[(size_t)(k0 + ty + i) * HID + n0 + tx];
    __syncthreads();
    #pragma unroll
    for (int i = 0; i < 32; i += 8)
        g_WoTf[(size_t)(n0 + ty + i) * HID + k0 + tx] = __float2half(t[tx][ty + i]);
}

__global__ void vt_transpose(const __nv_bfloat16* __restrict__ Vh,
                             const __nv_bfloat16* __restrict__ Vl,
                             __nv_bfloat16* __restrict__ VTh,
                             __nv_bfloat16* __restrict__ VTl)
{
    __shared__ __nv_bfloat16 th[32][34], tl[32][34];
    int s0 = blockIdx.x * 32, d0 = blockIdx.y * 32, bh = blockIdx.z;
    int bb = bh >> 2, hkv = bh & 3;
    int tx = threadIdx.x, ty = threadIdx.y;
    #pragma unroll
    for (int i = 0; i < 32; i += 8) {
        size_t src = (size_t)(bb * S + s0 + ty + i) * (NKV * DH) + hkv * DH + d0 + tx;
        th[ty + i][tx] = Vh[src];
        tl[ty + i][tx] = Vl[src];
    }
    __syncthreads();
    #pragma unroll
    for (int i = 0; i < 32; i += 8) {
        size_t dst = (size_t)(bh * DH + d0 + ty + i) * S + s0 + tx;
        VTh[dst] = th[tx][ty + i];
        VTl[dst] = tl[tx][ty + i];
    }
}

// ---------------------------------------------------------------------------
// GEMM cores: single-product fp16, CTA tile 128x128, 2-stage cp.async.
// 1/3 the MMAs of the old split-bf16 path.
// ---------------------------------------------------------------------------
#define KC   32
#define ASTR 40
#define GT_E (128 * ASTR)
#define STG_E (2 * GT_E)
#define GEMM_SMEM (2 * STG_E * 2)   // 41 KB

#define GEMM_MAINLOOP(Asrc, Bsrc, Kdim)                                          \
    const __half* srcs[2] = { Asrc, Bsrc };                                      \
    const int rowbase[2] = { m0, n0 };                                           \
    const int KI = (Kdim) / KC;                                                  \
    _Pragma("unroll")                                                            \
    for (int t = 0; t < 2; t++) {                                                \
        size_t g = (size_t)(rowbase[t] + ldr) * (Kdim) + ldc;                    \
        uint32_t d = sbase + (uint32_t)(t * GT_E + ldr * ASTR + ldc) * 2;        \
        CPA16(d, srcs[t] + g);                                                   \
        CPA16(d + 16, srcs[t] + g + 8);                                          \
    }                                                                            \
    CP_COMMIT();                                                                 \
    for (int kt = 0; kt < KI; kt++) {                                            \
        const int cur = kt & 1;                                                  \
        if (kt + 1 < KI) {                                                       \
            const int nxt = (kt + 1) & 1;                                        \
            int k0 = (kt + 1) * KC;                                              \
            _Pragma("unroll")                                                    \
            for (int t = 0; t < 2; t++) {                                        \
                size_t g = (size_t)(rowbase[t] + ldr) * (Kdim) + k0 + ldc;       \
                uint32_t d = sbase + (uint32_t)(nxt * STG_E + t * GT_E + ldr * ASTR + ldc) * 2; \
                CPA16(d, srcs[t] + g);                                           \
                CPA16(d + 16, srcs[t] + g + 8);                                  \
            }                                                                    \
            CP_COMMIT();                                                         \
            CP_WAIT(1);                                                          \
        } else {                                                                 \
            CP_WAIT(0);                                                          \
        }                                                                        \
        __syncthreads();                                                         \
        const uint32_t sA = sbase + (uint32_t)(cur * STG_E) * 2;                 \
        const uint32_t sB = sA + (uint32_t)GT_E * 2;                             \
        _Pragma("unroll")                                                        \
        for (int kk = 0; kk < KC; kk += 16) {                                    \
            uint32_t af[2][4], bf[4][4];                                         \
            _Pragma("unroll")                                                    \
            for (int mi = 0; mi < 2; mi++)                                       \
                ldmx4(af[mi], sA + ((wm + mi * 16 + a_row) * ASTR + kk + a_col) * 2); \
            _Pragma("unroll")                                                    \
            for (int t = 0; t < 4; t++)                                          \
                ldmx4(bf[t], sB + ((wn + t * 16 + b_row) * ASTR + kk + b_col) * 2); \
            _Pragma("unroll")                                                    \
            for (int nj = 0; nj < 8; nj++)                                       \
                _Pragma("unroll")                                                \
                for (int mi = 0; mi < 2; mi++)                                   \
                    mma16816h(acc[mi][nj], af[mi], &bf[nj >> 1][(nj & 1) * 2]);  \
        }                                                                        \
        __syncthreads();                                                         \
    }

#define GEMM_PREAMBLE                                                  \
    extern __shared__ __half smg[];                                    \
    const uint32_t sbase = smem_u32(smg);                              \
    const int tid = threadIdx.x, wid = tid >> 5, lane = tid & 31;      \
    const int wm = (wid & 3) * 32;                                     \
    const int wn = (wid >> 2) * 64;                                    \
    const int m0 = blockIdx.y * 128, n0 = blockIdx.x * 128;            \
    const int ldr = tid >> 1;                                          \
    const int ldc = (tid & 1) * 16;                                    \
    const int a_row = (lane & 15), a_col = (lane >> 4) * 8;            \
    const int b_row = (lane & 7) + ((lane >> 4) << 3), b_col = ((lane >> 3) & 1) * 8; \
    float acc[2][8][4] = {};

__global__ void __launch_bounds__(256, 2)
gemm_qkv()
{
    GEMM_PREAMBLE
    GEMM_MAINLOOP(g_Xf, g_WqkvTf, HID)

    __nv_bfloat16 *dh, *dl;
    int ldcn, coff;
    if (n0 < HID)            { dh = g_Qh; dl = g_Ql; ldcn = HID; coff = n0; }
    else if (n0 < HID + 256) { dh = g_Kh; dl = g_Kl; ldcn = 256; coff = n0 - HID; }
    else                     { dh = g_Vh; dl = g_Vl; ldcn = 256; coff = n0 - HID - 256; }

    #pragma unroll
    for (int mi = 0; mi < 2; mi++) {
        int row = m0 + wm + mi * 16 + (lane >> 2);
        #pragma unroll
        for (int nj = 0; nj < 8; nj++) {
            int col = coff + wn + nj * 8 + (lane & 3) * 2;
            float l0, l1, l2, l3;
            uint32_t h01 = pack_hi(acc[mi][nj][0], acc[mi][nj][1], l0, l1);
            uint32_t h23 = pack_hi(acc[mi][nj][2], acc[mi][nj][3], l2, l3);
            *(uint32_t*)&dh[(size_t)row * ldcn + col]       = h01;
            *(uint32_t*)&dl[(size_t)row * ldcn + col]       = pack_bf(l0, l1);
            *(uint32_t*)&dh[(size_t)(row + 8) * ldcn + col] = h23;
            *(uint32_t*)&dl[(size_t)(row + 8) * ldcn + col] = pack_bf(l2, l3);
        }
    }
}

__global__ void __launch_bounds__(256, 2)
gemm_out(float* __restrict__ C)
{
    GEMM_PREAMBLE
    GEMM_MAINLOOP(g_Af, g_WoTf, HID)

    #pragma unroll
    for (int mi = 0; mi < 2; mi++) {
        int row = m0 + wm + mi * 16 + (lane >> 2);
        #pragma unroll
        for (int nj = 0; nj < 8; nj++) {
            int col = n0 + wn + nj * 8 + (lane & 3) * 2;
            *(float2*)&C[(size_t)row * HID + col]       = make_float2(acc[mi][nj][0], acc[mi][nj][1]);
            *(float2*)&C[(size_t)(row + 8) * HID + col] = make_float2(acc[mi][nj][2], acc[mi][nj][3]);
        }
    }
}

// ---------------------------------------------------------------------------
// Flash attention (round-13 config: split-bf16, 2 CTAs/SM); epilogue -> fp16 A
// ---------------------------------------------------------------------------
#define TSTR 72
#define QT_E (128 * TSTR)
#define KV_E (64 * TSTR)
#define ATTN_SMEM ((2 * QT_E + 2 * 4 * KV_E) * 2)

__global__ void __launch_bounds__(256, 2)
attn_mma(const float* __restrict__ bias, __half* __restrict__ Af)
{
    extern __shared__ __nv_bfloat16 smb[];
    const uint32_t aQh = smem_u32(smb);
    const uint32_t aQl = aQh + QT_E * 2;
    const uint32_t kvbase = aQl + QT_E * 2;

    const int tid = threadIdx.x, wid = tid >> 5, lane = tid & 31;
    const int qt = blockIdx.x, h = blockIdx.y, bb = blockIdx.z;
    const int hkv = h >> 2;
    const int wm = wid * 16;

    const int a_row = (lane & 15), a_col = (lane >> 4) * 8;
    const int b_row = (lane & 7) + ((lane >> 4) << 3), b_col = ((lane >> 3) & 1) * 8;
    const int r = lane >> 2, qc = (lane & 3) * 2;

    #pragma unroll
    for (int i = 0; i < 4; i++) {
        int idx = tid + i * 256;
        int rr = idx >> 3, c = (idx & 7) * 8;
        size_t g = (size_t)(bb * S + qt * 128 + rr) * (NH * DH) + h * DH + c;
        *(uint4*)(smb + rr * TSTR + c)          = *(const uint4*)&g_Qh[g];
        *(uint4*)(smb + QT_E + rr * TSTR + c)   = *(const uint4*)&g_Ql[g];
    }

    const __nv_bfloat16* kvsrc[4];
    kvsrc[0] = g_Kh + (size_t)bb * S * (NKV * DH) + hkv * DH;
    kvsrc[1] = g_Kl + (size_t)bb * S * (NKV * DH) + hkv * DH;
    kvsrc[2] = g_VTh + (size_t)((bb * NKV + hkv) * DH) * S;
    kvsrc[3] = g_VTl + (size_t)((bb * NKV + hkv) * DH) * S;

    const int ltile = tid >> 6;
    const int lidx = tid & 63;

    #pragma unroll
    for (int j = 0; j < 8; j++) {
        int ch = lidx + j * 64;
        int rr = ch >> 3, c = (ch & 7) * 8;
        uint32_t d = kvbase + (uint32_t)(ltile * KV_E + rr * TSTR + c) * 2;
        size_t g = (ltile < 2) ? (size_t)rr * (NKV * DH) + c
                               : (size_t)rr * S + c;
        CPA16(d, kvsrc[ltile] + g);
    }
    CP_COMMIT();

    float oacc[8][4] = {};
    float m0 = -INFINITY, m1 = -INFINITY, l0 = 0.f, l1 = 0.f;
    const int row0 = qt * 128 + wm + r;
    const float* bprow = bias + ((size_t)(bb * NH + h) * S + row0) * S + qc;
    const uint2* mrow0 = g_Mbits + (size_t)(bb * S + row0) * (S/64);
    const uint2* mrow1 = mrow0 + 8 * (S/64);

    for (int kt = 0; kt < S / 64; kt++) {
        const int cur = kt & 1;
        if (kt + 1 < S / 64) {
            const int nxt = (kt + 1) & 1;
            int s0 = (kt + 1) * 64;
            #pragma unroll
            for (int j = 0; j < 8; j++) {
                int ch = lidx + j * 64;
                int rr = ch >> 3, c = (ch & 7) * 8;
                uint32_t d = kvbase + (uint32_t)((nxt * 4 + ltile) * KV_E + rr * TSTR + c) * 2;
                size_t g = (ltile < 2) ? (size_t)(s0 + rr) * (NKV * DH) + c
                                       : (size_t)rr * S + s0 + c;
                CPA16(d, kvsrc[ltile] + g);
            }
            CP_COMMIT();
        }

        float2 bvA[8], bvB[8];
        const float* bp = bprow + (size_t)kt * 64;
        #pragma unroll
        for (int nj = 0; nj < 8; nj++) {
            bvA[nj] = *(const float2*)(bp + nj * 8);
            bvB[nj] = *(const float2*)(bp + 8 * S + nj * 8);
        }
        uint2 mwA = mrow0[kt], mwB = mrow1[kt];

        if (kt + 1 < S / 64) CP_WAIT(1); else CP_WAIT(0);
        __syncthreads();

        const uint32_t aKh = kvbase + (uint32_t)((cur * 4 + 0) * KV_E) * 2;
        const uint32_t aKl = kvbase + (uint32_t)((cur * 4 + 1) * KV_E) * 2;
        const uint32_t aVh = kvbase + (uint32_t)((cur * 4 + 2) * KV_E) * 2;
        const uint32_t aVl = kvbase + (uint32_t)((cur * 4 + 3) * KV_E) * 2;

        float sacc[8][4] = {};
        #pragma unroll
        for (int kk = 0; kk < 64; kk += 16) {
            uint32_t qh[4], ql[4], kh[4][4], kl[4][4];
            uint32_t offA = ((wm + a_row) * TSTR + kk + a_col) * 2;
            ldmx4(qh, aQh + offA);
            ldmx4(ql, aQl + offA);
            #pragma unroll
            for (int t = 0; t < 4; t++) {
                uint32_t offB = ((t * 16 + b_row) * TSTR + kk + b_col) * 2;
                ldmx4(kh[t], aKh + offB);
                ldmx4(kl[t], aKl + offB);
            }
            #pragma unroll
            for (int nj = 0; nj < 8; nj++)
                mma16816(sacc[nj], qh, &kh[nj >> 1][(nj & 1) * 2]);
            #pragma unroll
            for (int nj = 0; nj < 8; nj++)
                mma16816(sacc[nj], qh, &kl[nj >> 1][(nj & 1) * 2]);
            #pragma unroll
            for (int nj = 0; nj < 8; nj++)
                mma16816(sacc[nj], ql, &kh[nj >> 1][(nj & 1) * 2]);
        }

        #pragma unroll
        for (int nj = 0; nj < 8; nj++) {
            int bi = (lane & 3) + nj * 4;
            sacc[nj][0] = ((mwA.x >> bi) & 1) ? fmaf(sacc[nj][0], 0.125f, bvA[nj].x) : -1e9f;
            sacc[nj][1] = ((mwA.y >> bi) & 1) ? fmaf(sacc[nj][1], 0.125f, bvA[nj].y) : -1e9f;
            sacc[nj][2] = ((mwB.x >> bi) & 1) ? fmaf(sacc[nj][2], 0.125f, bvB[nj].x) : -1e9f;
            sacc[nj][3] = ((mwB.y >> bi) & 1) ? fmaf(sacc[nj][3], 0.125f, bvB[nj].y) : -1e9f;
        }

        float mx0 = -INFINITY, mx1 = -INFINITY;
        #pragma unroll
        for (int nj = 0; nj < 8; nj++) {
            mx0 = fmaxf(mx0, fmaxf(sacc[nj][0], sacc[nj][1]));
            mx1 = fmaxf(mx1, fmaxf(sacc[nj][2], sacc[nj][3]));
        }
        mx0 = fmaxf(mx0, __shfl_xor_sync(0xffffffffu, mx0, 1));
        mx0 = fmaxf(mx0, __shfl_xor_sync(0xffffffffu, mx0, 2));
        mx1 = fmaxf(mx1, __shfl_xor_sync(0xffffffffu, mx1, 1));
        mx1 = fmaxf(mx1, __shfl_xor_sync(0xffffffffu, mx1, 2));
        float mn0 = fmaxf(m0, mx0), mn1 = fmaxf(m1, mx1);
        float alpha0 = fast_exp(m0 - mn0), alpha1 = fast_exp(m1 - mn1);
        m0 = mn0; m1 = mn1;

        float ts0 = 0.f, ts1 = 0.f;
        uint32_t ph[8][2], pl[8][2];
        #pragma unroll
        for (int nj = 0; nj < 8; nj++) {
            float p0 = fast_exp(sacc[nj][0] - mn0);
            float p1 = fast_exp(sacc[nj][1] - mn0);
            float p2 = fast_exp(sacc[nj][2] - mn1);
            float p3 = fast_exp(sacc[nj][3] - mn1);
            ts0 += p0 + p1;
            ts1 += p2 + p3;
            float q0, q1, q2, q3;
            ph[nj][0] = pack_hi(p0, p1, q0, q1);
            ph[nj][1] = pack_hi(p2, p3, q2, q3);
            pl[nj][0] = pack_bf(q0, q1);
            pl[nj][1] = pack_bf(q2, q3);
        }
        ts0 += __shfl_xor_sync(0xffffffffu, ts0, 1);
        ts0 += __shfl_xor_sync(0xffffffffu, ts0, 2);
        ts1 += __shfl_xor_sync(0xffffffffu, ts1, 1);
        ts1 += __shfl_xor_sync(0xffffffffu, ts1, 2);
        l0 = l0 * alpha0 + ts0;
        l1 = l1 * alpha1 + ts1;

        #pragma unroll
        for (int nj = 0; nj < 8; nj++) {
            oacc[nj][0] *= alpha0; oacc[nj][1] *= alpha0;
            oacc[nj][2] *= alpha1; oacc[nj][3] *= alpha1;
        }

        #pragma unroll
        for (int kk = 0; kk < 64; kk += 16) {
            int nt = kk >> 3;
            uint32_t aPh[4] = { ph[nt][0], ph[nt][1], ph[nt + 1][0], ph[nt + 1][1] };
            uint32_t aPl[4] = { pl[nt][0], pl[nt][1], pl[nt + 1][0], pl[nt + 1][1] };
            uint32_t vh[4][4], vl[4][4];
            #pragma unroll
            for (int t = 0; t < 4; t++) {
                uint32_t offV = ((t * 16 + b_row) * TSTR + kk + b_col) * 2;
                ldmx4(vh[t], aVh + offV);
                ldmx4(vl[t], aVl + offV);
            }
            #pragma unroll
            for (int nj = 0; nj < 8; nj++)
                mma16816(oacc[nj], aPh, &vh[nj >> 1][(nj & 1) * 2]);
            #pragma unroll
            for (int nj = 0; nj < 8; nj++)
                mma16816(oacc[nj], aPh, &vl[nj >> 1][(nj & 1) * 2]);
            #pragma unroll
            for (int nj = 0; nj < 8; nj++)
                mma16816(oacc[nj], aPl, &vh[nj >> 1][(nj & 1) * 2]);
        }
        __syncthreads();
    }

    // epilogue: normalize, write fp16 A
    float inv0 = 1.0f / l0, inv1 = 1.0f / l1;
    int rowA = bb * S + qt * 128 + wm + r;
    #pragma unroll
    for (int nj = 0; nj < 8; nj++) {
        int col = h * DH + nj * 8 + qc;
        *(uint32_t*)&Af[(size_t)rowA * HID + col]       = pack_f16(oacc[nj][0] * inv0, oacc[nj][1] * inv0);
        *(uint32_t*)&Af[(size_t)(rowA + 8) * HID + col] = pack_f16(oacc[nj][2] * inv1, oacc[nj][3] * inv1);
    }
}

// ---------------------------------------------------------------------------
extern "C" void kernel_launch(void* const* d_in, const int* in_sizes, int n_in,
                              void* d_out, int out_size)
{
    const float* X    = (const float*)d_in[0];
    const float* bias = (const float*)d_in[1];
    const int*   mask = (const int*  )d_in[2];
    const float* Wq   = (const float*)d_in[3];
    const float* Wk   = (const float*)d_in[4];
    const float* Wv   = (const float*)d_in[5];
    const float* Wo   = (const float*)d_in[6];
    float* out = (float*)d_out;

    __half *pXf, *pAf;
    __nv_bfloat16 *pVh, *pVl, *pVTh, *pVTl;
    cudaGetSymbolAddress((void**)&pXf, g_Xf);
    cudaGetSymbolAddress((void**)&pAf, g_Af);
    cudaGetSymbolAddress((void**)&pVh, g_Vh);    cudaGetSymbolAddress((void**)&pVl, g_Vl);
    cudaGetSymbolAddress((void**)&pVTh, g_VTh);  cudaGetSymbolAddress((void**)&pVTl, g_VTl);

    cudaFuncSetAttribute(gemm_qkv, cudaFuncAttributeMaxDynamicSharedMemorySize, GEMM_SMEM);
    cudaFuncSetAttribute(gemm_out, cudaFuncAttributeMaxDynamicSharedMemorySize, GEMM_SMEM);
    cudaFuncSetAttribute(attn_mma, cudaFuncAttributeMaxDynamicSharedMemorySize, ATTN_SMEM);

    split_kernel<<<(B*S*HID/4 + 255)/256, 256>>>(X, pXf, B*S*HID/4);            // 0
    maskpack<<<B*S, 512>>>(mask);                                               // 1
    transpose_qkv<<<dim3(NQKV/32, HID/32), dim3(32, 8)>>>(Wq, Wk, Wv);          // 2
    gemm_qkv<<<dim3(NQKV/128, (B*S)/128), 256, GEMM_SMEM>>>();                  // 3
    vt_transpose<<<dim3(S/32, DH/32, B*NKV), dim3(32, 8)>>>(pVh, pVl, pVTh, pVTl); // 4
    attn_mma<<<dim3(S/128, NH, B), 256, ATTN_SMEM>>>(bias, pAf);                // 5
    transpose_wo<<<dim3(HID/32, HID/32), dim3(32, 8)>>>(Wo);                    // 6
    gemm_out<<<dim3(HID/128, (B*S)/128), 256, GEMM_SMEM>>>(out);                // 7
}

// round 16
// speedup vs baseline: 1.8522x; 1.3552x over previous
#include <cuda_runtime.h>
#include <cuda_bf16.h>
#include <cuda_fp16.h>
#include <math.h>
#include <stdint.h>

#define B   4
#define S   1024
#define HID 1024
#define NH  16
#define NKV 4
#define DH  64
#define NQKV (HID + 2 * NKV * DH)   // 1536

// ---------------------------------------------------------------------------
// Scratch (allocation-free rule: __device__ globals)
// ---------------------------------------------------------------------------
__device__ __half g_Xf[B*S*HID];
__device__ __half g_WqkvTf[NQKV*HID];
__device__ __half g_WoTf[HID*HID];
__device__ __half g_Af[B*S*HID];
__device__ __half g_Qf[B*S*NH*DH];
__device__ __half g_Kf[B*S*NKV*DH];
__device__ __half g_Vf[B*S*NKV*DH];
__device__ __half g_VTf[B*NKV*DH*S];    // [b][hkv][d][s]
__device__ uint2 g_Mbits[B*S*(S/64)];

// ---------------------------------------------------------------------------
// helpers
// ---------------------------------------------------------------------------
__device__ __forceinline__ uint32_t smem_u32(const void* p) {
    uint32_t a;
    asm("{ .reg .u64 t; cvta.to.shared.u64 t, %1; cvt.u32.u64 %0, t; }" : "=r"(a) : "l"(p));
    return a;
}
__device__ __forceinline__ void ldmx4(uint32_t* r, uint32_t addr) {
    asm volatile("ldmatrix.sync.aligned.m8n8.x4.shared.b16 {%0,%1,%2,%3}, [%4];"
                 : "=r"(r[0]), "=r"(r[1]), "=r"(r[2]), "=r"(r[3]) : "r"(addr));
}
__device__ __forceinline__ void mma16816h(float* d, const uint32_t* a, const uint32_t* b) {
    asm volatile("mma.sync.aligned.m16n8k16.row.col.f32.f16.f16.f32 "
                 "{%0,%1,%2,%3}, {%4,%5,%6,%7}, {%8,%9}, {%0,%1,%2,%3};"
                 : "+f"(d[0]), "+f"(d[1]), "+f"(d[2]), "+f"(d[3])
                 : "r"(a[0]), "r"(a[1]), "r"(a[2]), "r"(a[3]), "r"(b[0]), "r"(b[1]));
}
__device__ __forceinline__ uint32_t pack_f16(float a, float b) {
    uint32_t r;
    asm("cvt.rn.f16x2.f32 %0, %1, %2;" : "=r"(r) : "f"(b), "f"(a));
    return r;
}
__device__ __forceinline__ float fast_exp(float x) {
    const float LOG2E = 1.4426950408889634f;
    x = fmaxf(x, -87.0f);
    float z  = fmaf(x, LOG2E, 12582912.0f);
    float nf = z - 12582912.0f;
    float f  = fmaf(x, LOG2E, -nf);
    float p  = 1.33978436e-3f;
    p = fmaf(p, f, 9.67795525e-3f);
    p = fmaf(p, f, 5.55072727e-2f);
    p = fmaf(p, f, 2.40226419e-1f);
    p = fmaf(p, f, 6.93147182e-1f);
    p = fmaf(p, f, 1.0f);
    uint32_t sc = (uint32_t)(__float_as_int(z) + (127 - 0x4B400000)) << 23;
    return __uint_as_float(sc) * p;
}
#define CPA16(dst, src) asm volatile("cp.async.cg.shared.global [%0], [%1], 16;" :: "r"(dst), "l"(src))
#define CP_COMMIT()     asm volatile("cp.async.commit_group;")
#define CP_WAIT(n)      asm volatile("cp.async.wait_group %0;" :: "n"(n))

// ---------------------------------------------------------------------------
// prep kernels
// ---------------------------------------------------------------------------
__global__ void split_kernel(const float* __restrict__ x,
                             __half* __restrict__ hf, int n4)
{
    int i = blockIdx.x * 256 + threadIdx.x;
    if (i >= n4) return;
    float4 v = ((const float4*)x)[i];
    ((uint32_t*)hf)[2*i]   = pack_f16(v.x, v.y);
    ((uint32_t*)hf)[2*i+1] = pack_f16(v.z, v.w);
}

__global__ void maskpack(const int* __restrict__ mask)
{
    int row = blockIdx.x;
    int w = threadIdx.x >> 5, lane = threadIdx.x & 31;
    int2 m = *(const int2*)(mask + (size_t)row * S + w * 64 + lane * 2);
    uint32_t b0 = __ballot_sync(0xffffffffu, m.x != 0);
    uint32_t b1 = __ballot_sync(0xffffffffu, m.y != 0);
    if (lane == 0) g_Mbits[row * (S/64) + w] = make_uint2(b0, b1);
}

__global__ void transpose_qkv(const float* __restrict__ Wq,
                              const float* __restrict__ Wk,
                              const float* __restrict__ Wv)
{
    __shared__ float t[32][33];
    int n0 = blockIdx.x * 32, k0 = blockIdx.y * 32;
    int tx = threadIdx.x, ty = threadIdx.y;
    const float* W;
    int N, nc;
    if (n0 < HID)            { W = Wq; N = HID; nc = n0; }
    else if (n0 < HID + 256) { W = Wk; N = 256; nc = n0 - HID; }
    else                     { W = Wv; N = 256; nc = n0 - HID - 256; }
    #pragma unroll
    for (int i = 0; i < 32; i += 8)
        t[ty + i][tx] = W[(size_t)(k0 + ty + i) * N + nc + tx];
    __syncthreads();
    #pragma unroll
    for (int i = 0; i < 32; i += 8)
        g_WqkvTf[(size_t)(n0 + ty + i) * HID + k0 + tx] = __float2half(t[tx][ty + i]);
}

__global__ void transpose_wo(const float* __restrict__ W)
{
    __shared__ float t[32][33];
    int n0 = blockIdx.x * 32, k0 = blockIdx.y * 32;
    int tx = threadIdx.x, ty = threadIdx.y;
    #pragma unroll
    for (int i = 0; i < 32; i += 8)
        t[ty + i][tx] = W[(size_t)(k0 + ty + i) * HID + n0 + tx];
    __syncthreads();
    #pragma unroll
    for (int i = 0; i < 32; i += 8)
        g_WoTf[(size_t)(n0 + ty + i) * HID + k0 + tx] = __float2half(t[tx][ty + i]);
}

__global__ void vt_transpose(const __half* __restrict__ Vf,
                             __half* __restrict__ VTf)
{
    __shared__ __half t[32][34];
    int s0 = blockIdx.x * 32, d0 = blockIdx.y * 32, bh = blockIdx.z;
    int bb = bh >> 2, hkv = bh & 3;
    int tx = threadIdx.x, ty = threadIdx.y;
    #pragma unroll
    for (int i = 0; i < 32; i += 8)
        t[ty + i][tx] = Vf[(size_t)(bb * S + s0 + ty + i) * (NKV * DH) + hkv * DH + d0 + tx];
    __syncthreads();
    #pragma unroll
    for (int i = 0; i < 32; i += 8)
        VTf[(size_t)(bh * DH + d0 + ty + i) * S + s0 + tx] = t[tx][ty + i];
}

// ---------------------------------------------------------------------------
// GEMM cores: single-product fp16, CTA tile 128x128, 2-stage cp.async.
// ---------------------------------------------------------------------------
#define KC   32
#define ASTR 40
#define GT_E (128 * ASTR)
#define STG_E (2 * GT_E)
#define GEMM_SMEM (2 * STG_E * 2)

#define GEMM_MAINLOOP(Asrc, Bsrc, Kdim)                                          \
    const __half* srcs[2] = { Asrc, Bsrc };                                      \
    const int rowbase[2] = { m0, n0 };                                           \
    const int KI = (Kdim) / KC;                                                  \
    _Pragma("unroll")                                                            \
    for (int t = 0; t < 2; t++) {                                                \
        size_t g = (size_t)(rowbase[t] + ldr) * (Kdim) + ldc;                    \
        uint32_t d = sbase + (uint32_t)(t * GT_E + ldr * ASTR + ldc) * 2;        \
        CPA16(d, srcs[t] + g);                                                   \
        CPA16(d + 16, srcs[t] + g + 8);                                          \
    }                                                                            \
    CP_COMMIT();                                                                 \
    for (int kt = 0; kt < KI; kt++) {                                            \
        const int cur = kt & 1;                                                  \
        if (kt + 1 < KI) {                                                       \
            const int nxt = (kt + 1) & 1;                                        \
            int k0 = (kt + 1) * KC;                                              \
            _Pragma("unroll")                                                    \
            for (int t = 0; t < 2; t++) {                                        \
                size_t g = (size_t)(rowbase[t] + ldr) * (Kdim) + k0 + ldc;       \
                uint32_t d = sbase + (uint32_t)(nxt * STG_E + t * GT_E + ldr * ASTR + ldc) * 2; \
                CPA16(d, srcs[t] + g);                                           \
                CPA16(d + 16, srcs[t] + g + 8);                                  \
            }                                                                    \
            CP_COMMIT();                                                         \
            CP_WAIT(1);                                                          \
        } else {                                                                 \
            CP_WAIT(0);                                                          \
        }                                                                        \
        __syncthreads();                                                         \
        const uint32_t sA = sbase + (uint32_t)(cur * STG_E) * 2;                 \
        const uint32_t sB = sA + (uint32_t)GT_E * 2;                             \
        _Pragma("unroll")                                                        \
        for (int kk = 0; kk < KC; kk += 16) {                                    \
            uint32_t af[2][4], bf[4][4];                                         \
            _Pragma("unroll")                                                    \
            for (int mi = 0; mi < 2; mi++)                                       \
                ldmx4(af[mi], sA + ((wm + mi * 16 + a_row) * ASTR + kk + a_col) * 2); \
            _Pragma("unroll")                                                    \
            for (int t = 0; t < 4; t++)                                          \
                ldmx4(bf[t], sB + ((wn + t * 16 + b_row) * ASTR + kk + b_col) * 2); \
            _Pragma("unroll")                                                    \
            for (int nj = 0; nj < 8; nj++)                                       \
                _Pragma("unroll")                                                \
                for (int mi = 0; mi < 2; mi++)                                   \
                    mma16816h(acc[mi][nj], af[mi], &bf[nj >> 1][(nj & 1) * 2]);  \
        }                                                                        \
        __syncthreads();                                                         \
    }

#define GEMM_PREAMBLE                                                  \
    extern __shared__ __half smg[];                                    \
    const uint32_t sbase = smem_u32(smg);                              \
    const int tid = threadIdx.x, wid = tid >> 5, lane = tid & 31;      \
    const int wm = (wid & 3) * 32;                                     \
    const int wn = (wid >> 2) * 64;                                    \
    const int m0 = blockIdx.y * 128, n0 = blockIdx.x * 128;            \
    const int ldr = tid >> 1;                                          \
    const int ldc = (tid & 1) * 16;                                    \
    const int a_row = (lane & 15), a_col = (lane >> 4) * 8;            \
    const int b_row = (lane & 7) + ((lane >> 4) << 3), b_col = ((lane >> 3) & 1) * 8; \
    float acc[2][8][4] = {};

__global__ void __launch_bounds__(256, 2)
gemm_qkv()
{
    GEMM_PREAMBLE
    GEMM_MAINLOOP(g_Xf, g_WqkvTf, HID)

    __half* df;
    int ldcn, coff;
    if (n0 < HID)            { df = g_Qf; ldcn = HID; coff = n0; }
    else if (n0 < HID + 256) { df = g_Kf; ldcn = 256; coff = n0 - HID; }
    else                     { df = g_Vf; ldcn = 256; coff = n0 - HID - 256; }

    #pragma unroll
    for (int mi = 0; mi < 2; mi++) {
        int row = m0 + wm + mi * 16 + (lane >> 2);
        #pragma unroll
        for (int nj = 0; nj < 8; nj++) {
            int col = coff + wn + nj * 8 + (lane & 3) * 2;
            *(uint32_t*)&df[(size_t)row * ldcn + col]       = pack_f16(acc[mi][nj][0], acc[mi][nj][1]);
            *(uint32_t*)&df[(size_t)(row + 8) * ldcn + col] = pack_f16(acc[mi][nj][2], acc[mi][nj][3]);
        }
    }
}

__global__ void __launch_bounds__(256, 2)
gemm_out(float* __restrict__ C)
{
    GEMM_PREAMBLE
    GEMM_MAINLOOP(g_Af, g_WoTf, HID)

    #pragma unroll
    for (int mi = 0; mi < 2; mi++) {
        int row = m0 + wm + mi * 16 + (lane >> 2);
        #pragma unroll
        for (int nj = 0; nj < 8; nj++) {
            int col = n0 + wn + nj * 8 + (lane & 3) * 2;
            *(float2*)&C[(size_t)row * HID + col]       = make_float2(acc[mi][nj][0], acc[mi][nj][1]);
            *(float2*)&C[(size_t)(row + 8) * HID + col] = make_float2(acc[mi][nj][2], acc[mi][nj][3]);
        }
    }
}

// ---------------------------------------------------------------------------
// Flash attention: single-product fp16 QK^T and PV. 64 MMAs per k-tile per
// warp (was 192). 2-stage cp.async K/V, 2 CTAs/SM.
// ---------------------------------------------------------------------------
#define TSTR 72
#define QT_E (128 * TSTR)
#define KV_E (64 * TSTR)
#define ATTN_SMEM ((QT_E + 2 * 2 * KV_E) * 2)   // 55296 B

__global__ void __launch_bounds__(256, 2)
attn_mma(const float* __restrict__ bias, __half* __restrict__ Af)
{
    extern __shared__ __half smh[];
    const uint32_t aQ = smem_u32(smh);
    const uint32_t kvbase = aQ + QT_E * 2;

    const int tid = threadIdx.x, wid = tid >> 5, lane = tid & 31;
    const int qt = blockIdx.x, h = blockIdx.y, bb = blockIdx.z;
    const int hkv = h >> 2;
    const int wm = wid * 16;

    const int a_row = (lane & 15), a_col = (lane >> 4) * 8;
    const int b_row = (lane & 7) + ((lane >> 4) << 3), b_col = ((lane >> 3) & 1) * 8;
    const int r = lane >> 2, qc = (lane & 3) * 2;

    // Q tile [128 x 64] fp16
    #pragma unroll
    for (int i = 0; i < 4; i++) {
        int idx = tid + i * 256;
        int rr = idx >> 3, c = (idx & 7) * 8;
        size_t g = (size_t)(bb * S + qt * 128 + rr) * (NH * DH) + h * DH + c;
        *(uint4*)(smh + rr * TSTR + c) = *(const uint4*)&g_Qf[g];
    }

    const __half* kvsrc[2];
    kvsrc[0] = g_Kf + (size_t)bb * S * (NKV * DH) + hkv * DH;
    kvsrc[1] = g_VTf + (size_t)((bb * NKV + hkv) * DH) * S;

    const int ltile = tid >> 7;        // 0 = K, 1 = VT
    const int lidx = tid & 127;        // 128 threads per tile, 4 chunks each

    #pragma unroll
    for (int j = 0; j < 4; j++) {
        int ch = lidx + j * 128;       // 0..511
        int rr = ch >> 3, c = (ch & 7) * 8;
        uint32_t d = kvbase + (uint32_t)(ltile * KV_E + rr * TSTR + c) * 2;
        size_t g = (ltile == 0) ? (size_t)rr * (NKV * DH) + c
                                : (size_t)rr * S + c;
        CPA16(d, kvsrc[ltile] + g);
    }
    CP_COMMIT();

    float oacc[8][4] = {};
    float m0 = -INFINITY, m1 = -INFINITY, l0 = 0.f, l1 = 0.f;
    const int row0 = qt * 128 + wm + r;
    const float* bprow = bias + ((size_t)(bb * NH + h) * S + row0) * S + qc;
    const uint2* mrow0 = g_Mbits + (size_t)(bb * S + row0) * (S/64);
    const uint2* mrow1 = mrow0 + 8 * (S/64);

    for (int kt = 0; kt < S / 64; kt++) {
        const int cur = kt & 1;
        if (kt + 1 < S / 64) {
            const int nxt = (kt + 1) & 1;
            int s0 = (kt + 1) * 64;
            #pragma unroll
            for (int j = 0; j < 4; j++) {
                int ch = lidx + j * 128;
                int rr = ch >> 3, c = (ch & 7) * 8;
                uint32_t d = kvbase + (uint32_t)((nxt * 2 + ltile) * KV_E + rr * TSTR + c) * 2;
                size_t g = (ltile == 0) ? (size_t)(s0 + rr) * (NKV * DH) + c
                                        : (size_t)rr * S + s0 + c;
                CPA16(d, kvsrc[ltile] + g);
            }
            CP_COMMIT();
        }

        float2 bvA[8], bvB[8];
        const float* bp = bprow + (size_t)kt * 64;
        #pragma unroll
        for (int nj = 0; nj < 8; nj++) {
            bvA[nj] = *(const float2*)(bp + nj * 8);
            bvB[nj] = *(const float2*)(bp + 8 * S + nj * 8);
        }
        uint2 mwA = mrow0[kt], mwB = mrow1[kt];

        if (kt + 1 < S / 64) CP_WAIT(1); else CP_WAIT(0);
        __syncthreads();

        const uint32_t aK = kvbase + (uint32_t)(cur * 2 * KV_E) * 2;
        const uint32_t aV = aK + (uint32_t)KV_E * 2;

        // S = Q K^T (single fp16 product)
        float sacc[8][4] = {};
        #pragma unroll
        for (int kk = 0; kk < 64; kk += 16) {
            uint32_t qf[4], kf[4][4];
            ldmx4(qf, aQ + ((wm + a_row) * TSTR + kk + a_col) * 2);
            #pragma unroll
            for (int t = 0; t < 4; t++)
                ldmx4(kf[t], aK + ((t * 16 + b_row) * TSTR + kk + b_col) * 2);
            #pragma unroll
            for (int nj = 0; nj < 8; nj++)
                mma16816h(sacc[nj], qf, &kf[nj >> 1][(nj & 1) * 2]);
        }

        #pragma unroll
        for (int nj = 0; nj < 8; nj++) {
            int bi = (lane & 3) + nj * 4;
            sacc[nj][0] = ((mwA.x >> bi) & 1) ? fmaf(sacc[nj][0], 0.125f, bvA[nj].x) : -1e9f;
            sacc[nj][1] = ((mwA.y >> bi) & 1) ? fmaf(sacc[nj][1], 0.125f, bvA[nj].y) : -1e9f;
            sacc[nj][2] = ((mwB.x >> bi) & 1) ? fmaf(sacc[nj][2], 0.125f, bvB[nj].x) : -1e9f;
            sacc[nj][3] = ((mwB.y >> bi) & 1) ? fmaf(sacc[nj][3], 0.125f, bvB[nj].y) : -1e9f;
        }

        float mx0 = -INFINITY, mx1 = -INFINITY;
        #pragma unroll
        for (int nj = 0; nj < 8; nj++) {
            mx0 = fmaxf(mx0, fmaxf(sacc[nj][0], sacc[nj][1]));
            mx1 = fmaxf(mx1, fmaxf(sacc[nj][2], sacc[nj][3]));
        }
        mx0 = fmaxf(mx0, __shfl_xor_sync(0xffffffffu, mx0, 1));
        mx0 = fmaxf(mx0, __shfl_xor_sync(0xffffffffu, mx0, 2));
        mx1 = fmaxf(mx1, __shfl_xor_sync(0xffffffffu, mx1, 1));
        mx1 = fmaxf(mx1, __shfl_xor_sync(0xffffffffu, mx1, 2));
        float mn0 = fmaxf(m0, mx0), mn1 = fmaxf(m1, mx1);
        float alpha0 = fast_exp(m0 - mn0), alpha1 = fast_exp(m1 - mn1);
        m0 = mn0; m1 = mn1;

        float ts0 = 0.f, ts1 = 0.f;
        uint32_t pf[8][2];
        #pragma unroll
        for (int nj = 0; nj < 8; nj++) {
            float p0 = fast_exp(sacc[nj][0] - mn0);
            float p1 = fast_exp(sacc[nj][1] - mn0);
            float p2 = fast_exp(sacc[nj][2] - mn1);
            float p3 = fast_exp(sacc[nj][3] - mn1);
            ts0 += p0 + p1;
            ts1 += p2 + p3;
            pf[nj][0] = pack_f16(p0, p1);
            pf[nj][1] = pack_f16(p2, p3);
        }
        ts0 += __shfl_xor_sync(0xffffffffu, ts0, 1);
        ts0 += __shfl_xor_sync(0xffffffffu, ts0, 2);
        ts1 += __shfl_xor_sync(0xffffffffu, ts1, 1);
        ts1 += __shfl_xor_sync(0xffffffffu, ts1, 2);
        l0 = l0 * alpha0 + ts0;
        l1 = l1 * alpha1 + ts1;

        #pragma unroll
        for (int nj = 0; nj < 8; nj++) {
            oacc[nj][0] *= alpha0; oacc[nj][1] *= alpha0;
            oacc[nj][2] *= alpha1; oacc[nj][3] *= alpha1;
        }

        // O += P @ V (single fp16 product)
        #pragma unroll
        for (int kk = 0; kk < 64; kk += 16) {
            int nt = kk >> 3;
            uint32_t aPf[4] = { pf[nt][0], pf[nt][1], pf[nt + 1][0], pf[nt + 1][1] };
            uint32_t vf[4][4];
            #pragma unroll
            for (int t = 0; t < 4; t++)
                ldmx4(vf[t], aV + ((t * 16 + b_row) * TSTR + kk + b_col) * 2);
            #pragma unroll
            for (int nj = 0; nj < 8; nj++)
                mma16816h(oacc[nj], aPf, &vf[nj >> 1][(nj & 1) * 2]);
        }
        __syncthreads();
    }

    // epilogue: normalize, write fp16 A
    float inv0 = 1.0f / l0, inv1 = 1.0f / l1;
    int rowA = bb * S + qt * 128 + wm + r;
    #pragma unroll
    for (int nj = 0; nj < 8; nj++) {
        int col = h * DH + nj * 8 + qc;
        *(uint32_t*)&Af[(size_t)rowA * HID + col]       = pack_f16(oacc[nj][0] * inv0, oacc[nj][1] * inv0);
        *(uint32_t*)&Af[(size_t)(rowA + 8) * HID + col] = pack_f16(oacc[nj][2] * inv1, oacc[nj][3] * inv1);
    }
}

// ---------------------------------------------------------------------------
extern "C" void kernel_launch(void* const* d_in, const int* in_sizes, int n_in,
                              void* d_out, int out_size)
{
    const float* X    = (const float*)d_in[0];
    const float* bias = (const float*)d_in[1];
    const int*   mask = (const int*  )d_in[2];
    const float* Wq   = (const float*)d_in[3];
    const float* Wk   = (const float*)d_in[4];
    const float* Wv   = (const float*)d_in[5];
    const float* Wo   = (const float*)d_in[6];
    float* out = (float*)d_out;

    __half *pXf, *pAf, *pVf, *pVTf;
    cudaGetSymbolAddress((void**)&pXf, g_Xf);
    cudaGetSymbolAddress((void**)&pAf, g_Af);
    cudaGetSymbolAddress((void**)&pVf, g_Vf);
    cudaGetSymbolAddress((void**)&pVTf, g_VTf);

    cudaFuncSetAttribute(gemm_qkv, cudaFuncAttributeMaxDynamicSharedMemorySize, GEMM_SMEM);
    cudaFuncSetAttribute(gemm_out, cudaFuncAttributeMaxDynamicSharedMemorySize, GEMM_SMEM);
    cudaFuncSetAttribute(attn_mma, cudaFuncAttributeMaxDynamicSharedMemorySize, ATTN_SMEM);

    split_kernel<<<(B*S*HID/4 + 255)/256, 256>>>(X, pXf, B*S*HID/4);            // 0
    maskpack<<<B*S, 512>>>(mask);                                               // 1
    transpose_qkv<<<dim3(NQKV/32, HID/32), dim3(32, 8)>>>(Wq, Wk, Wv);          // 2
    gemm_qkv<<<dim3(NQKV/128, (B*S)/128), 256, GEMM_SMEM>>>();                  // 3
    vt_transpose<<<dim3(S/32, DH/32, B*NKV), dim3(32, 8)>>>(pVf, pVTf);         // 4
    attn_mma<<<dim3(S/128, NH, B), 256, ATTN_SMEM>>>(bias, pAf);                // 5
    transpose_wo<<<dim3(HID/32, HID/32), dim3(32, 8)>>>(Wo);                    // 6
    gemm_out<<<dim3(HID/128, (B*S)/128), 256, GEMM_SMEM>>>(out);                // 7
}

// round 17
// speedup vs baseline: 2.0171x; 1.0891x over previous
#include <cuda_runtime.h>
#include <cuda_bf16.h>
#include <cuda_fp16.h>
#include <math.h>
#include <stdint.h>

#define B   4
#define S   1024
#define HID 1024
#define NH  16
#define NKV 4
#define DH  64
#define NQKV (HID + 2 * NKV * DH)   // 1536

// ---------------------------------------------------------------------------
// Scratch (allocation-free rule: __device__ globals)
// ---------------------------------------------------------------------------
__device__ __half g_Xf[B*S*HID];
__device__ __half g_WqkvTf[NQKV*HID];
__device__ __half g_WoTf[HID*HID];
__device__ __half g_Af[B*S*HID];
__device__ __half g_Qf[B*S*NH*DH];
__device__ __half g_Kf[B*S*NKV*DH];
__device__ __half g_Vf[B*S*NKV*DH];
__device__ __half g_VTf[B*NKV*DH*S];    // [b][hkv][d][s]
__device__ uint2 g_Mbits[B*S*(S/64)];

// ---------------------------------------------------------------------------
// helpers
// ---------------------------------------------------------------------------
__device__ __forceinline__ uint32_t smem_u32(const void* p) {
    uint32_t a;
    asm("{ .reg .u64 t; cvta.to.shared.u64 t, %1; cvt.u32.u64 %0, t; }" : "=r"(a) : "l"(p));
    return a;
}
__device__ __forceinline__ void ldmx4(uint32_t* r, uint32_t addr) {
    asm volatile("ldmatrix.sync.aligned.m8n8.x4.shared.b16 {%0,%1,%2,%3}, [%4];"
                 : "=r"(r[0]), "=r"(r[1]), "=r"(r[2]), "=r"(r[3]) : "r"(addr));
}
__device__ __forceinline__ void mma16816h(float* d, const uint32_t* a, const uint32_t* b) {
    asm volatile("mma.sync.aligned.m16n8k16.row.col.f32.f16.f16.f32 "
                 "{%0,%1,%2,%3}, {%4,%5,%6,%7}, {%8,%9}, {%0,%1,%2,%3};"
                 : "+f"(d[0]), "+f"(d[1]), "+f"(d[2]), "+f"(d[3])
                 : "r"(a[0]), "r"(a[1]), "r"(a[2]), "r"(a[3]), "r"(b[0]), "r"(b[1]));
}
__device__ __forceinline__ uint32_t pack_f16(float a, float b) {
    uint32_t r;
    asm("cvt.rn.f16x2.f32 %0, %1, %2;" : "=r"(r) : "f"(b), "f"(a));
    return r;
}
// MUFU EX2: 2^x, handles very negative x -> 0
__device__ __forceinline__ float ex2(float x) {
    float r;
    asm("ex2.approx.f32 %0, %1;" : "=f"(r) : "f"(x));
    return r;
}
#define LOG2E 1.4426950408889634f
#define CPA16(dst, src) asm volatile("cp.async.cg.shared.global [%0], [%1], 16;" :: "r"(dst), "l"(src))
#define CP_COMMIT()     asm volatile("cp.async.commit_group;")
#define CP_WAIT(n)      asm volatile("cp.async.wait_group %0;" :: "n"(n))

// ---------------------------------------------------------------------------
// prep kernels
// ---------------------------------------------------------------------------
__global__ void split_kernel(const float* __restrict__ x,
                             __half* __restrict__ hf, int n4)
{
    int i = blockIdx.x * 256 + threadIdx.x;
    if (i >= n4) return;
    float4 v = ((const float4*)x)[i];
    ((uint32_t*)hf)[2*i]   = pack_f16(v.x, v.y);
    ((uint32_t*)hf)[2*i+1] = pack_f16(v.z, v.w);
}

__global__ void maskpack(const int* __restrict__ mask)
{
    int row = blockIdx.x;
    int w = threadIdx.x >> 5, lane = threadIdx.x & 31;
    int2 m = *(const int2*)(mask + (size_t)row * S + w * 64 + lane * 2);
    uint32_t b0 = __ballot_sync(0xffffffffu, m.x != 0);
    uint32_t b1 = __ballot_sync(0xffffffffu, m.y != 0);
    if (lane == 0) g_Mbits[row * (S/64) + w] = make_uint2(b0, b1);
}

__global__ void transpose_qkv(const float* __restrict__ Wq,
                              const float* __restrict__ Wk,
                              const float* __restrict__ Wv)
{
    __shared__ float t[32][33];
    int n0 = blockIdx.x * 32, k0 = blockIdx.y * 32;
    int tx = threadIdx.x, ty = threadIdx.y;
    const float* W;
    int N, nc;
    if (n0 < HID)            { W = Wq; N = HID; nc = n0; }
    else if (n0 < HID + 256) { W = Wk; N = 256; nc = n0 - HID; }
    else                     { W = Wv; N = 256; nc = n0 - HID - 256; }
    #pragma unroll
    for (int i = 0; i < 32; i += 8)
        t[ty + i][tx] = W[(size_t)(k0 + ty + i) * N + nc + tx];
    __syncthreads();
    #pragma unroll
    for (int i = 0; i < 32; i += 8)
        g_WqkvTf[(size_t)(n0 + ty + i) * HID + k0 + tx] = __float2half(t[tx][ty + i]);
}

__global__ void transpose_wo(const float* __restrict__ W)
{
    __shared__ float t[32][33];
    int n0 = blockIdx.x * 32, k0 = blockIdx.y * 32;
    int tx = threadIdx.x, ty = threadIdx.y;
    #pragma unroll
    for (int i = 0; i < 32; i += 8)
        t[ty + i][tx] = W[(size_t)(k0 + ty + i) * HID + n0 + tx];
    __syncthreads();
    #pragma unroll
    for (int i = 0; i < 32; i += 8)
        g_WoTf[(size_t)(n0 + ty + i) * HID + k0 + tx] = __float2half(t[tx][ty + i]);
}

__global__ void vt_transpose(const __half* __restrict__ Vf,
                             __half* __restrict__ VTf)
{
    __shared__ __half t[32][34];
    int s0 = blockIdx.x * 32, d0 = blockIdx.y * 32, bh = blockIdx.z;
    int bb = bh >> 2, hkv = bh & 3;
    int tx = threadIdx.x, ty = threadIdx.y;
    #pragma unroll
    for (int i = 0; i < 32; i += 8)
        t[ty + i][tx] = Vf[(size_t)(bb * S + s0 + ty + i) * (NKV * DH) + hkv * DH + d0 + tx];
    __syncthreads();
    #pragma unroll
    for (int i = 0; i < 32; i += 8)
        VTf[(size_t)(bh * DH + d0 + ty + i) * S + s0 + tx] = t[tx][ty + i];
}

// ---------------------------------------------------------------------------
// GEMM cores: single-product fp16, CTA tile 128x128, 2-stage cp.async.
// ---------------------------------------------------------------------------
#define KC   32
#define ASTR 40
#define GT_E (128 * ASTR)
#define STG_E (2 * GT_E)
#define GEMM_SMEM (2 * STG_E * 2)

#define GEMM_MAINLOOP(Asrc, Bsrc, Kdim)                                          \
    const __half* srcs[2] = { Asrc, Bsrc };                                      \
    const int rowbase[2] = { m0, n0 };                                           \
    const int KI = (Kdim) / KC;                                                  \
    _Pragma("unroll")                                                            \
    for (int t = 0; t < 2; t++) {                                                \
        size_t g = (size_t)(rowbase[t] + ldr) * (Kdim) + ldc;                    \
        uint32_t d = sbase + (uint32_t)(t * GT_E + ldr * ASTR + ldc) * 2;        \
        CPA16(d, srcs[t] + g);                                                   \
        CPA16(d + 16, srcs[t] + g + 8);                                          \
    }                                                                            \
    CP_COMMIT();                                                                 \
    for (int kt = 0; kt < KI; kt++) {                                            \
        const int cur = kt & 1;                                                  \
        if (kt + 1 < KI) {                                                       \
            const int nxt = (kt + 1) & 1;                                        \
            int k0 = (kt + 1) * KC;                                              \
            _Pragma("unroll")                                                    \
            for (int t = 0; t < 2; t++) {                                        \
                size_t g = (size_t)(rowbase[t] + ldr) * (Kdim) + k0 + ldc;       \
                uint32_t d = sbase + (uint32_t)(nxt * STG_E + t * GT_E + ldr * ASTR + ldc) * 2; \
                CPA16(d, srcs[t] + g);                                           \
                CPA16(d + 16, srcs[t] + g + 8);                                  \
            }                                                                    \
            CP_COMMIT();                                                         \
            CP_WAIT(1);                                                          \
        } else {                                                                 \
            CP_WAIT(0);                                                          \
        }                                                                        \
        __syncthreads();                                                         \
        const uint32_t sA = sbase + (uint32_t)(cur * STG_E) * 2;                 \
        const uint32_t sB = sA + (uint32_t)GT_E * 2;                             \
        _Pragma("unroll")                                                        \
        for (int kk = 0; kk < KC; kk += 16) {                                    \
            uint32_t af[2][4], bf[4][4];                                         \
            _Pragma("unroll")                                                    \
            for (int mi = 0; mi < 2; mi++)                                       \
                ldmx4(af[mi], sA + ((wm + mi * 16 + a_row) * ASTR + kk + a_col) * 2); \
            _Pragma("unroll")                                                    \
            for (int t = 0; t < 4; t++)                                          \
                ldmx4(bf[t], sB + ((wn + t * 16 + b_row) * ASTR + kk + b_col) * 2); \
            _Pragma("unroll")                                                    \
            for (int nj = 0; nj < 8; nj++)                                       \
                _Pragma("unroll")                                                \
                for (int mi = 0; mi < 2; mi++)                                   \
                    mma16816h(acc[mi][nj], af[mi], &bf[nj >> 1][(nj & 1) * 2]);  \
        }                                                                        \
        __syncthreads();                                                         \
    }

#define GEMM_PREAMBLE                                                  \
    extern __shared__ __half smg[];                                    \
    const uint32_t sbase = smem_u32(smg);                              \
    const int tid = threadIdx.x, wid = tid >> 5, lane = tid & 31;      \
    const int wm = (wid & 3) * 32;                                     \
    const int wn = (wid >> 2) * 64;                                    \
    const int m0 = blockIdx.y * 128, n0 = blockIdx.x * 128;            \
    const int ldr = tid >> 1;                                          \
    const int ldc = (tid & 1) * 16;                                    \
    const int a_row = (lane & 15), a_col = (lane >> 4) * 8;            \
    const int b_row = (lane & 7) + ((lane >> 4) << 3), b_col = ((lane >> 3) & 1) * 8; \
    float acc[2][8][4] = {};

__global__ void __launch_bounds__(256, 2)
gemm_qkv()
{
    GEMM_PREAMBLE
    GEMM_MAINLOOP(g_Xf, g_WqkvTf, HID)

    __half* df;
    int ldcn, coff;
    if (n0 < HID)            { df = g_Qf; ldcn = HID; coff = n0; }
    else if (n0 < HID + 256) { df = g_Kf; ldcn = 256; coff = n0 - HID; }
    else                     { df = g_Vf; ldcn = 256; coff = n0 - HID - 256; }

    #pragma unroll
    for (int mi = 0; mi < 2; mi++) {
        int row = m0 + wm + mi * 16 + (lane >> 2);
        #pragma unroll
        for (int nj = 0; nj < 8; nj++) {
            int col = coff + wn + nj * 8 + (lane & 3) * 2;
            *(uint32_t*)&df[(size_t)row * ldcn + col]       = pack_f16(acc[mi][nj][0], acc[mi][nj][1]);
            *(uint32_t*)&df[(size_t)(row + 8) * ldcn + col] = pack_f16(acc[mi][nj][2], acc[mi][nj][3]);
        }
    }
}

__global__ void __launch_bounds__(256, 2)
gemm_out(float* __restrict__ C)
{
    GEMM_PREAMBLE
    GEMM_MAINLOOP(g_Af, g_WoTf, HID)

    #pragma unroll
    for (int mi = 0; mi < 2; mi++) {
        int row = m0 + wm + mi * 16 + (lane >> 2);
        #pragma unroll
        for (int nj = 0; nj < 8; nj++) {
            int col = n0 + wn + nj * 8 + (lane & 3) * 2;
            *(float2*)&C[(size_t)row * HID + col]       = make_float2(acc[mi][nj][0], acc[mi][nj][1]);
            *(float2*)&C[(size_t)(row + 8) * HID + col] = make_float2(acc[mi][nj][2], acc[mi][nj][3]);
        }
    }
}

// ---------------------------------------------------------------------------
// Flash attention: fp16 single-product QK^T / PV; log2-domain softmax with
// MUFU ex2 (1 op/element on the MUFU pipe instead of 11 fma ops).
// ---------------------------------------------------------------------------
#define TSTR 72
#define QT_E (128 * TSTR)
#define KV_E (64 * TSTR)
#define ATTN_SMEM ((QT_E + 2 * 2 * KV_E) * 2)   // 55296 B

__global__ void __launch_bounds__(256, 2)
attn_mma(const float* __restrict__ bias, __half* __restrict__ Af)
{
    extern __shared__ __half smh[];
    const uint32_t aQ = smem_u32(smh);
    const uint32_t kvbase = aQ + QT_E * 2;

    const int tid = threadIdx.x, wid = tid >> 5, lane = tid & 31;
    const int qt = blockIdx.x, h = blockIdx.y, bb = blockIdx.z;
    const int hkv = h >> 2;
    const int wm = wid * 16;

    const int a_row = (lane & 15), a_col = (lane >> 4) * 8;
    const int b_row = (lane & 7) + ((lane >> 4) << 3), b_col = ((lane >> 3) & 1) * 8;
    const int r = lane >> 2, qc = (lane & 3) * 2;

    #pragma unroll
    for (int i = 0; i < 4; i++) {
        int idx = tid + i * 256;
        int rr = idx >> 3, c = (idx & 7) * 8;
        size_t g = (size_t)(bb * S + qt * 128 + rr) * (NH * DH) + h * DH + c;
        *(uint4*)(smh + rr * TSTR + c) = *(const uint4*)&g_Qf[g];
    }

    const __half* kvsrc[2];
    kvsrc[0] = g_Kf + (size_t)bb * S * (NKV * DH) + hkv * DH;
    kvsrc[1] = g_VTf + (size_t)((bb * NKV + hkv) * DH) * S;

    const int ltile = tid >> 7;
    const int lidx = tid & 127;

    #pragma unroll
    for (int j = 0; j < 4; j++) {
        int ch = lidx + j * 128;
        int rr = ch >> 3, c = (ch & 7) * 8;
        uint32_t d = kvbase + (uint32_t)(ltile * KV_E + rr * TSTR + c) * 2;
        size_t g = (ltile == 0) ? (size_t)rr * (NKV * DH) + c
                                : (size_t)rr * S + c;
        CPA16(d, kvsrc[ltile] + g);
    }
    CP_COMMIT();

    float oacc[8][4] = {};
    // running max m* and sums l* live in LOG2 domain for m, linear for l
    float m0 = -INFINITY, m1 = -INFINITY, l0 = 0.f, l1 = 0.f;
    const int row0 = qt * 128 + wm + r;
    const float* bprow = bias + ((size_t)(bb * NH + h) * S + row0) * S + qc;
    const uint2* mrow0 = g_Mbits + (size_t)(bb * S + row0) * (S/64);
    const uint2* mrow1 = mrow0 + 8 * (S/64);
    const float SC = 0.125f * LOG2E;

    for (int kt = 0; kt < S / 64; kt++) {
        const int cur = kt & 1;
        if (kt + 1 < S / 64) {
            const int nxt = (kt + 1) & 1;
            int s0 = (kt + 1) * 64;
            #pragma unroll
            for (int j = 0; j < 4; j++) {
                int ch = lidx + j * 128;
                int rr = ch >> 3, c = (ch & 7) * 8;
                uint32_t d = kvbase + (uint32_t)((nxt * 2 + ltile) * KV_E + rr * TSTR + c) * 2;
                size_t g = (ltile == 0) ? (size_t)(s0 + rr) * (NKV * DH) + c
                                        : (size_t)rr * S + s0 + c;
                CPA16(d, kvsrc[ltile] + g);
            }
            CP_COMMIT();
        }

        float2 bvA[8], bvB[8];
        const float* bp = bprow + (size_t)kt * 64;
        #pragma unroll
        for (int nj = 0; nj < 8; nj++) {
            bvA[nj] = *(const float2*)(bp + nj * 8);
            bvB[nj] = *(const float2*)(bp + 8 * S + nj * 8);
        }
        uint2 mwA = mrow0[kt], mwB = mrow1[kt];

        if (kt + 1 < S / 64) CP_WAIT(1); else CP_WAIT(0);
        __syncthreads();

        const uint32_t aK = kvbase + (uint32_t)(cur * 2 * KV_E) * 2;
        const uint32_t aV = aK + (uint32_t)KV_E * 2;

        float sacc[8][4] = {};
        #pragma unroll
        for (int kk = 0; kk < 64; kk += 16) {
            uint32_t qf[4], kf[4][4];
            ldmx4(qf, aQ + ((wm + a_row) * TSTR + kk + a_col) * 2);
            #pragma unroll
            for (int t = 0; t < 4; t++)
                ldmx4(kf[t], aK + ((t * 16 + b_row) * TSTR + kk + b_col) * 2);
            #pragma unroll
            for (int nj = 0; nj < 8; nj++)
                mma16816h(sacc[nj], qf, &kf[nj >> 1][(nj & 1) * 2]);
        }

        // log2-domain: s2 = sacc*(0.125*log2e) + bias*log2e; mask -> -1e9
        #pragma unroll
        for (int nj = 0; nj < 8; nj++) {
            int bi = (lane & 3) + nj * 4;
            sacc[nj][0] = ((mwA.x >> bi) & 1) ? fmaf(sacc[nj][0], SC, bvA[nj].x * LOG2E) : -1e9f;
            sacc[nj][1] = ((mwA.y >> bi) & 1) ? fmaf(sacc[nj][1], SC, bvA[nj].y * LOG2E) : -1e9f;
            sacc[nj][2] = ((mwB.x >> bi) & 1) ? fmaf(sacc[nj][2], SC, bvB[nj].x * LOG2E) : -1e9f;
            sacc[nj][3] = ((mwB.y >> bi) & 1) ? fmaf(sacc[nj][3], SC, bvB[nj].y * LOG2E) : -1e9f;
        }

        float mx0 = -INFINITY, mx1 = -INFINITY;
        #pragma unroll
        for (int nj = 0; nj < 8; nj++) {
            mx0 = fmaxf(mx0, fmaxf(sacc[nj][0], sacc[nj][1]));
            mx1 = fmaxf(mx1, fmaxf(sacc[nj][2], sacc[nj][3]));
        }
        mx0 = fmaxf(mx0, __shfl_xor_sync(0xffffffffu, mx0, 1));
        mx0 = fmaxf(mx0, __shfl_xor_sync(0xffffffffu, mx0, 2));
        mx1 = fmaxf(mx1, __shfl_xor_sync(0xffffffffu, mx1, 1));
        mx1 = fmaxf(mx1, __shfl_xor_sync(0xffffffffu, mx1, 2));
        float mn0 = fmaxf(m0, mx0), mn1 = fmaxf(m1, mx1);
        float alpha0 = ex2(m0 - mn0), alpha1 = ex2(m1 - mn1);
        m0 = mn0; m1 = mn1;

        float ts0 = 0.f, ts1 = 0.f;
        uint32_t pf[8][2];
        #pragma unroll
        for (int nj = 0; nj < 8; nj++) {
            float p0 = ex2(sacc[nj][0] - mn0);
            float p1 = ex2(sacc[nj][1] - mn0);
            float p2 = ex2(sacc[nj][2] - mn1);
            float p3 = ex2(sacc[nj][3] - mn1);
            ts0 += p0 + p1;
            ts1 += p2 + p3;
            pf[nj][0] = pack_f16(p0, p1);
            pf[nj][1] = pack_f16(p2, p3);
        }
        ts0 += __shfl_xor_sync(0xffffffffu, ts0, 1);
        ts0 += __shfl_xor_sync(0xffffffffu, ts0, 2);
        ts1 += __shfl_xor_sync(0xffffffffu, ts1, 1);
        ts1 += __shfl_xor_sync(0xffffffffu, ts1, 2);
        l0 = l0 * alpha0 + ts0;
        l1 = l1 * alpha1 + ts1;

        #pragma unroll
        for (int nj = 0; nj < 8; nj++) {
            oacc[nj][0] *= alpha0; oacc[nj][1] *= alpha0;
            oacc[nj][2] *= alpha1; oacc[nj][3] *= alpha1;
        }

        #pragma unroll
        for (int kk = 0; kk < 64; kk += 16) {
            int nt = kk >> 3;
            uint32_t aPf[4] = { pf[nt][0], pf[nt][1], pf[nt + 1][0], pf[nt + 1][1] };
            uint32_t vf[4][4];
            #pragma unroll
            for (int t = 0; t < 4; t++)
                ldmx4(vf[t], aV + ((t * 16 + b_row) * TSTR + kk + b_col) * 2);
            #pragma unroll
            for (int nj = 0; nj < 8; nj++)
                mma16816h(oacc[nj], aPf, &vf[nj >> 1][(nj & 1) * 2]);
        }
        __syncthreads();
    }

    float inv0 = 1.0f / l0, inv1 = 1.0f / l1;
    int rowA = bb * S + qt * 128 + wm + r;
    #pragma unroll
    for (int nj = 0; nj < 8; nj++) {
        int col = h * DH + nj * 8 + qc;
        *(uint32_t*)&Af[(size_t)rowA * HID + col]       = pack_f16(oacc[nj][0] * inv0, oacc[nj][1] * inv0);
        *(uint32_t*)&Af[(size_t)(rowA + 8) * HID + col] = pack_f16(oacc[nj][2] * inv1, oacc[nj][3] * inv1);
    }
}

// ---------------------------------------------------------------------------
extern "C" void kernel_launch(void* const* d_in, const int* in_sizes, int n_in,
                              void* d_out, int out_size)
{
    const float* X    = (const float*)d_in[0];
    const float* bias = (const float*)d_in[1];
    const int*   mask = (const int*  )d_in[2];
    const float* Wq   = (const float*)d_in[3];
    const float* Wk   = (const float*)d_in[4];
    const float* Wv   = (const float*)d_in[5];
    const float* Wo   = (const float*)d_in[6];
    float* out = (float*)d_out;

    __half *pXf, *pAf, *pVf, *pVTf;
    cudaGetSymbolAddress((void**)&pXf, g_Xf);
    cudaGetSymbolAddress((void**)&pAf, g_Af);
    cudaGetSymbolAddress((void**)&pVf, g_Vf);
    cudaGetSymbolAddress((void**)&pVTf, g_VTf);

    cudaFuncSetAttribute(gemm_qkv, cudaFuncAttributeMaxDynamicSharedMemorySize, GEMM_SMEM);
    cudaFuncSetAttribute(gemm_out, cudaFuncAttributeMaxDynamicSharedMemorySize, GEMM_SMEM);
    cudaFuncSetAttribute(attn_mma, cudaFuncAttributeMaxDynamicSharedMemorySize, ATTN_SMEM);

    split_kernel<<<(B*S*HID/4 + 255)/256, 256>>>(X, pXf, B*S*HID/4);            // 0
    maskpack<<<B*S, 512>>>(mask);                                               // 1
    transpose_qkv<<<dim3(NQKV/32, HID/32), dim3(32, 8)>>>(Wq, Wk, Wv);          // 2
    gemm_qkv<<<dim3(NQKV/128, (B*S)/128), 256, GEMM_SMEM>>>();                  // 3
    vt_transpose<<<dim3(S/32, DH/32, B*NKV), dim3(32, 8)>>>(pVf, pVTf);         // 4
    attn_mma<<<dim3(S/128, NH, B), 256, ATTN_SMEM>>>(bias, pAf);                // 5
    transpose_wo<<<dim3(HID/32, HID/32), dim3(32, 8)>>>(Wo);                    // 6
    gemm_out<<<dim3(HID/128, (B*S)/128), 256, GEMM_SMEM>>>(out);                // 7
}